// round 7
// baseline (speedup 1.0000x reference)
#include <cuda_runtime.h>
#include <cuda_bf16.h>
#include <cstdint>

#define NNODES 65536
#define NEDGES 262144

// ============================ device scratch ============================
__device__ __align__(256) __nv_bfloat16 g_xb   [NNODES * 256];
__device__ __align__(256) __nv_bfloat16 g_hnode[NNODES * 128];
__device__ __align__(256) __nv_bfloat16 g_grow [NNODES * 256];
__device__ __align__(256) __nv_bfloat16 g_gcol [NNODES * 256];
__device__ __align__(256) __nv_bfloat16 g_h0   [(size_t)NEDGES * 256];
__device__ __align__(256) __nv_bfloat16 g_Bx [128 * 256];
__device__ __align__(256) __nv_bfloat16 g_B0a[256 * 128];
__device__ __align__(256) __nv_bfloat16 g_B0b[256 * 128];
// int8 mid-layer weight image in MMA-fragment order:
// u64 index = slot*4096 + kgl*1024 + tile*32 + lane, slot = layer*2 + khalf
__device__ __align__(256) uint2 g_Bq[65536];
__device__ int g_idx64;

// ============================ PTX helpers (base PTX only) ============================
__device__ __forceinline__ uint32_t smem_u32(const void* p) {
    uint32_t a;
    asm("{ .reg .u64 t; cvta.to.shared.u64 t, %1; cvt.u32.u64 %0, t; }" : "=r"(a) : "l"(p));
    return a;
}
__device__ __forceinline__ void cp16(uint32_t dst, const void* src) {
    asm volatile("cp.async.cg.shared.global [%0], [%1], 16;" :: "r"(dst), "l"(src));
}
__device__ __forceinline__ void cp_commit() {
    asm volatile("cp.async.commit_group;" ::: "memory");
}
template <int N>
__device__ __forceinline__ void cp_wait() {
    asm volatile("cp.async.wait_group %0;" :: "n"(N) : "memory");
}
__device__ __forceinline__ void ldm_x4(uint32_t* r, uint32_t addr) {
    asm volatile("ldmatrix.sync.aligned.m8n8.x4.shared.b16 {%0,%1,%2,%3}, [%4];"
                 : "=r"(r[0]), "=r"(r[1]), "=r"(r[2]), "=r"(r[3]) : "r"(addr));
}
__device__ __forceinline__ void ldm_x2(uint32_t* r, uint32_t addr) {
    asm volatile("ldmatrix.sync.aligned.m8n8.x2.shared.b16 {%0,%1}, [%2];"
                 : "=r"(r[0]), "=r"(r[1]) : "r"(addr));
}
__device__ __forceinline__ void mma_bf16(float* c, const uint32_t* a, const uint32_t* b) {
    asm volatile(
        "mma.sync.aligned.m16n8k16.row.col.f32.bf16.bf16.f32 "
        "{%0,%1,%2,%3}, {%4,%5,%6,%7}, {%8,%9}, {%0,%1,%2,%3};"
        : "+f"(c[0]), "+f"(c[1]), "+f"(c[2]), "+f"(c[3])
        : "r"(a[0]), "r"(a[1]), "r"(a[2]), "r"(a[3]), "r"(b[0]), "r"(b[1]));
}
__device__ __forceinline__ void mma_s8(int* c, const uint32_t* a, uint32_t b0, uint32_t b1) {
    asm volatile(
        "mma.sync.aligned.m16n8k32.row.col.s32.s8.s8.s32 "
        "{%0,%1,%2,%3}, {%4,%5,%6,%7}, {%8,%9}, {%0,%1,%2,%3};"
        : "+r"(c[0]), "+r"(c[1]), "+r"(c[2]), "+r"(c[3])
        : "r"(a[0]), "r"(a[1]), "r"(a[2]), "r"(a[3]), "r"(b0), "r"(b1));
}

// quantize 128 fp32 C-frag values (va[t][0..3]) to s8 A-fragments qa[32]
// va[t] = {rowg col2j, rowg col2j+1, rowg+8 col2j, rowg+8 col2j+1} of n-tile t.
__device__ __forceinline__ void quant_pack(const float va[32][4], float qs,
                                           uint32_t* qa, int lane) {
    const int j = lane & 3;
    const int src_lo = (lane & ~3) | (2 * (j & 1));
    const uint32_t sel = (j >> 1) ? 0x7632u : 0x5410u;
    #pragma unroll
    for (int tp = 0; tp < 16; tp++) {
        #pragma unroll
        for (int r = 0; r < 2; r++) {
            int i00 = __float2int_rn(va[2 * tp][2 * r] * qs);
            int i01 = __float2int_rn(va[2 * tp][2 * r + 1] * qs);
            int i10 = __float2int_rn(va[2 * tp + 1][2 * r] * qs);
            int i11 = __float2int_rn(va[2 * tp + 1][2 * r + 1] * qs);
            uint32_t p0 = __byte_perm((uint32_t)i00, (uint32_t)i01, 0x0040u);
            uint32_t p1 = __byte_perm((uint32_t)i10, (uint32_t)i11, 0x0040u);
            uint32_t P  = __byte_perm(p0, p1, 0x5410u);
            uint32_t vlo = __shfl_sync(0xffffffffu, P, src_lo);
            uint32_t vhi = __shfl_sync(0xffffffffu, P, src_lo + 1);
            qa[(tp >> 1) * 4 + (tp & 1) * 2 + r] = __byte_perm(vlo, vhi, sel);
        }
    }
}

// ============================ prep: everything in one launch ============================
__global__ void prep_everything(const float* __restrict__ x, const float* __restrict__ Wx,
                                const float* __restrict__ W0, const float* __restrict__ Wm,
                                const unsigned* __restrict__ ei) {
    if (blockIdx.x == 0 && threadIdx.x == 0) {
        int is64 = 1;
        for (int i = 0; i < 512; i++)
            if (ei[2 * i + 1] != 0u) { is64 = 0; break; }
        g_idx64 = is64;
    }
    const int stride = gridDim.x * blockDim.x;
    const int tid0 = blockIdx.x * blockDim.x + threadIdx.x;
    const int n1 = NNODES * 256;
    const int total = n1 + 32768 + 32768 + 32768 + 65536;
    for (int i = tid0; i < total; i += stride) {
        if (i < n1) {
            g_xb[i] = __float2bfloat16(x[i]);
        } else if (i < n1 + 32768) {                        // Bx [128][256]
            int t = i - n1;
            int n = t >> 8, k = t & 255;
            g_Bx[t] = __float2bfloat16(Wx[k * 128 + n]);
        } else if (i < n1 + 65536) {                        // B0a [256][128]
            int t = i - n1 - 32768;
            int n = t >> 7, k = t & 127;
            g_B0a[t] = __float2bfloat16(W0[k * 256 + n]);
        } else if (i < n1 + 98304) {                        // B0b [256][128]
            int t = i - n1 - 65536;
            int n = t >> 7, k = t & 127;
            g_B0b[t] = __float2bfloat16(W0[(128 + k) * 256 + n]);
        } else {                                            // int8 mid-weight fragments
            int t = i - n1 - 98304;                         // 0..65535
            int ls = t >> 12, kgl = (t >> 10) & 3;
            int tile = (t >> 5) & 31, ln = t & 31;
            int L = ls >> 1, kg = (ls & 1) * 4 + kgl;
            int n = tile * 8 + (ln >> 2), jj = ln & 3;
            const float* W = Wm + (size_t)L * 65536;
            uint32_t w2[2];
            #pragma unroll
            for (int h = 0; h < 2; h++) {
                int q[4];
                #pragma unroll
                for (int b = 0; b < 4; b++) {
                    int k = kg * 32 + h * 16 + 4 * jj + b;
                    float v = W[(size_t)k * 256 + n] * 2032.f;   // 127/ (1/16)
                    v = fminf(fmaxf(v, -127.f), 127.f);
                    q[b] = __float2int_rn(v);
                }
                w2[h] = __byte_perm(__byte_perm((uint32_t)q[0], (uint32_t)q[1], 0x0040u),
                                    __byte_perm((uint32_t)q[2], (uint32_t)q[3], 0x0040u),
                                    0x5410u);
            }
            g_Bq[t] = make_uint2(w2[0], w2[1]);
        }
    }
}

// ============================ generic bf16 HMMA GEMM (prep stages) ============================
template <int K, int NOUT, bool LEAKY, bool HASBIAS>
__global__ void __launch_bounds__(256)
gemm_mma(const __nv_bfloat16* __restrict__ A, const __nv_bfloat16* __restrict__ B,
         const float* __restrict__ bias, __nv_bfloat16* __restrict__ Out) {
    static_assert(K % 64 == 0, "");
    constexpr int KT = K / 64;
    extern __shared__ char smem[];
    const uint32_t sb = smem_u32(smem);
    constexpr uint32_t STAGE = 32768, BOFF = 16384;

    const int tid = threadIdx.x;
    const int lane = tid & 31, warp = tid >> 5;
    const int warp_m = warp & 1;
    const int warp_n = warp >> 1;
    const size_t m0 = (size_t)blockIdx.x * 128;
    const int n0 = blockIdx.y * 128;

    float acc[4][4][4];
    #pragma unroll
    for (int i = 0; i < 4; i++)
        #pragma unroll
        for (int j = 0; j < 4; j++)
            #pragma unroll
            for (int q = 0; q < 4; q++) acc[i][j][q] = 0.f;

    auto load_stage = [&](int stage, int kt) {
        const uint32_t base = sb + stage * STAGE;
        #pragma unroll
        for (int i = 0; i < 4; i++) {
            int idx = tid + i * 256;
            int r = idx >> 3, c8 = idx & 7;
            uint32_t dst = base + r * 128 + (((c8 ^ (r & 7))) << 4);
            cp16(dst, A + (m0 + r) * K + kt * 64 + c8 * 8);
        }
        #pragma unroll
        for (int i = 0; i < 4; i++) {
            int idx = tid + i * 256;
            int r = idx >> 3, c8 = idx & 7;
            uint32_t dst = base + BOFF + r * 128 + (((c8 ^ (r & 7))) << 4);
            cp16(dst, B + (size_t)(n0 + r) * K + kt * 64 + c8 * 8);
        }
    };

    load_stage(0, 0);
    cp_commit();

    for (int kt = 0; kt < KT; kt++) {
        if (kt + 1 < KT) { load_stage((kt + 1) & 1, kt + 1); cp_commit(); cp_wait<1>(); }
        else             { cp_wait<0>(); }
        __syncthreads();

        const uint32_t abase = sb + (kt & 1) * STAGE;
        const uint32_t bbase = abase + BOFF;
        #pragma unroll
        for (int ks = 0; ks < 4; ks++) {
            uint32_t af[4][4];
            #pragma unroll
            for (int mi = 0; mi < 4; mi++) {
                int r = warp_m * 64 + mi * 16 + (lane & 15);
                int c8 = ks * 2 + (lane >> 4);
                ldm_x4(af[mi], abase + r * 128 + ((c8 ^ (r & 7)) << 4));
            }
            uint32_t bf2[4][2];
            #pragma unroll
            for (int ni = 0; ni < 4; ni++) {
                int r = warp_n * 32 + ni * 8 + (lane & 7);
                int c8 = ks * 2 + ((lane >> 3) & 1);
                ldm_x2(bf2[ni], bbase + r * 128 + ((c8 ^ (r & 7)) << 4));
            }
            #pragma unroll
            for (int mi = 0; mi < 4; mi++)
                #pragma unroll
                for (int ni = 0; ni < 4; ni++)
                    mma_bf16(acc[mi][ni], af[mi], bf2[ni]);
        }
        __syncthreads();
    }

    const int g = lane >> 2;
    #pragma unroll
    for (int ni = 0; ni < 4; ni++) {
        const int col = n0 + warp_n * 32 + ni * 8 + ((lane & 3) << 1);
        float bb0 = 0.f, bb1 = 0.f;
        if (HASBIAS) { bb0 = __ldg(bias + col); bb1 = __ldg(bias + col + 1); }
        #pragma unroll
        for (int mi = 0; mi < 4; mi++) {
            const size_t r0 = m0 + warp_m * 64 + mi * 16 + g;
            float v0 = acc[mi][ni][0] + bb0, v1 = acc[mi][ni][1] + bb1;
            float v2 = acc[mi][ni][2] + bb0, v3 = acc[mi][ni][3] + bb1;
            if (LEAKY) {
                v0 = v0 >= 0.f ? v0 : 0.01f * v0;  v1 = v1 >= 0.f ? v1 : 0.01f * v1;
                v2 = v2 >= 0.f ? v2 : 0.01f * v2;  v3 = v3 >= 0.f ? v3 : 0.01f * v3;
            }
            __nv_bfloat162 p0 = __floats2bfloat162_rn(v0, v1);
            __nv_bfloat162 p1 = __floats2bfloat162_rn(v2, v3);
            *(uint32_t*)(Out + r0 * NOUT + col)       = *(uint32_t*)&p0;
            *(uint32_t*)(Out + (r0 + 8) * NOUT + col) = *(uint32_t*)&p1;
        }
    }
}

// ============================ gather + ea-matvec + combine ============================
__global__ void __launch_bounds__(256)
gather_combine_ea(const int* __restrict__ ei, const float* __restrict__ ea,
                  const float* __restrict__ W0, const float* __restrict__ b0,
                  const __nv_bfloat16* __restrict__ gr, const __nv_bfloat16* __restrict__ gc,
                  __nv_bfloat16* __restrict__ h0) {
    __shared__ float sea[64][16];
    __shared__ int srow[64], scol[64];
    const int t = threadIdx.x;
    const long e0 = (long)blockIdx.x * 64;
    const int is64 = g_idx64;
    if (t < 64) {
        long e = e0 + t;
        if (is64) { srow[t] = ei[2 * e]; scol[t] = ei[2 * (NEDGES + e)]; }
        else      { srow[t] = ei[e];     scol[t] = ei[NEDGES + e]; }
    }
    {
        int e = t >> 2, k = (t & 3) * 4;
        *(float4*)&sea[e][k] = *(const float4*)(ea + (e0 + e) * 16 + k);
    }
    const int cp = t & 127;
    float2 w[16];
    #pragma unroll
    for (int k = 0; k < 16; k++)
        w[k] = *(const float2*)(W0 + (size_t)(256 + k) * 256 + 2 * cp);
    const float2 bb = *(const float2*)(b0 + 2 * cp);
    __syncthreads();

    const int eo = t >> 7;
    for (int i = eo; i < 64; i += 2) {
        float v0 = bb.x, v1 = bb.y;
        #pragma unroll
        for (int k = 0; k < 16; k++) {
            float s = sea[i][k];
            v0 += s * w[k].x;
            v1 += s * w[k].y;
        }
        const __nv_bfloat162 gv = ((const __nv_bfloat162*)(gr + (size_t)srow[i] * 256))[cp];
        const __nv_bfloat162 cv = ((const __nv_bfloat162*)(gc + (size_t)scol[i] * 256))[cp];
        float2 gb = __bfloat1622float2(gv);
        float2 cb = __bfloat1622float2(cv);
        v0 += gb.x + cb.x;
        v1 += gb.y + cb.y;
        v0 = v0 >= 0.f ? v0 : 0.01f * v0;
        v1 = v1 >= 0.f ? v1 : 0.01f * v1;
        ((__nv_bfloat162*)(h0 + (size_t)(e0 + i) * 256))[cp] = __floats2bfloat162_rn(v0, v1);
    }
}

// ============================ fused 8 mid layers (INT8) + head ============================
// CTA = 128 edges, 8 warps x 16-row tiles. Weights s8 in fragment order, 4x32KB ring
// (one slot = half a layer's K). Activations quantized per-CTA per-layer with exact
// dynamic amax; C-frags repacked to next A-frags via byte_perm + quad shuffles.
__global__ void __launch_bounds__(256, 1)
fused_mid_q(const __nv_bfloat16* __restrict__ h0, const uint2* __restrict__ Bq,
            const float* __restrict__ bm, const float* __restrict__ Wl,
            const float* __restrict__ bl, float* __restrict__ out) {
    extern __shared__ char smem[];
    const uint32_t sb = smem_u32(smem);
    constexpr uint32_t RINGOFF = 65536;                 // ring: 4 x 32KB at [64K, 192K)
    constexpr uint32_t PARAM = 65536 + 131072;
    float* sbias = (float*)(smem + PARAM);              // 8 x 256 fp32
    float* sWl   = (float*)(smem + PARAM + 8192);       // 256 x 3 fp32
    float* sbl   = (float*)(smem + PARAM + 8192 + 3072);
    float* sred  = (float*)(smem + PARAM + 8192 + 3072 + 16);  // 8 floats

    const int tid = threadIdx.x, lane = tid & 31, warp = tid >> 5;
    const size_t m0 = (size_t)blockIdx.x * 128;

    for (int i = tid; i < 2048; i += 256) sbias[i] = bm[i];
    for (int i = tid; i < 768; i += 256) sWl[i] = Wl[i];
    if (tid < 3) sbl[tid] = bl[tid];

    // slot loader: slot s (0..15) = (layer s>>1, k-half s&1); region s&3; linear 32KB copy
    auto loadSlot = [&](int s) {
        const uint32_t base = sb + RINGOFF + (uint32_t)(s & 3) * 32768u;
        const char* src = (const char*)(Bq + (size_t)s * 4096);
        #pragma unroll
        for (int i = 0; i < 8; i++) {
            int idx = tid + i * 256;
            cp16(base + idx * 16, src + idx * 16);
        }
    };

    // A tile (h0 bf16, 128x256) -> [0,64KB) as 4 chunks of [128][64], XOR swizzle
    #pragma unroll
    for (int kc = 0; kc < 4; kc++)
        #pragma unroll
        for (int i = 0; i < 4; i++) {
            int idx = tid + i * 256;
            int r = idx >> 3, c8 = idx & 7;
            cp16(sb + kc * 16384 + r * 128 + ((c8 ^ (r & 7)) << 4),
                 h0 + (m0 + r) * 256 + kc * 64 + c8 * 8);
        }
    cp_commit();                  // G0 = A
    loadSlot(0); cp_commit();     // G1
    loadSlot(1); cp_commit();     // G2
    cp_wait<2>();                 // A ready
    __syncthreads();

    // ldmatrix A -> bf16 frags -> fp32 va
    float va[32][4];
    #pragma unroll
    for (int s = 0; s < 16; s++) {
        int rr = warp * 16 + (lane & 15);
        int cc = (s & 3) * 2 + (lane >> 4);
        uint32_t f[4];
        ldm_x4(f, sb + (s >> 2) * 16384 + rr * 128 + ((cc ^ (rr & 7)) << 4));
        float2 x0 = __bfloat1622float2(*(__nv_bfloat162*)&f[0]);
        float2 y0 = __bfloat1622float2(*(__nv_bfloat162*)&f[1]);
        float2 x1 = __bfloat1622float2(*(__nv_bfloat162*)&f[2]);
        float2 y1 = __bfloat1622float2(*(__nv_bfloat162*)&f[3]);
        va[2 * s][0] = x0.x; va[2 * s][1] = x0.y; va[2 * s][2] = y0.x; va[2 * s][3] = y0.y;
        va[2 * s + 1][0] = x1.x; va[2 * s + 1][1] = x1.y;
        va[2 * s + 1][2] = y1.x; va[2 * s + 1][3] = y1.y;
    }

    // per-CTA amax of h0 tile
    float lm = 0.f;
    #pragma unroll
    for (int t = 0; t < 32; t++)
        #pragma unroll
        for (int q = 0; q < 4; q++) lm = fmaxf(lm, fabsf(va[t][q]));
    #pragma unroll
    for (int o = 16; o; o >>= 1) lm = fmaxf(lm, __shfl_xor_sync(0xffffffffu, lm, o));
    if (lane == 0) sred[warp] = lm;
    __syncthreads();
    float amax = sred[0];
    #pragma unroll
    for (int w = 1; w < 8; w++) amax = fmaxf(amax, sred[w]);

    uint32_t qa[32];
    quant_pack(va, amax > 0.f ? 127.f / amax : 0.f, qa, lane);
    float aprev = amax;

    const int j = lane & 3;
    for (int l = 0; l < 8; ++l) {
        int acc[32][4];
        #pragma unroll
        for (int t = 0; t < 32; t++) { acc[t][0] = 0; acc[t][1] = 0; acc[t][2] = 0; acc[t][3] = 0; }

        #pragma unroll
        for (int hf = 0; hf < 2; hf++) {
            const int s = l * 2 + hf;
            cp_wait<1>();
            __syncthreads();
            if (s + 2 < 16) loadSlot(s + 2);
            cp_commit();
            const uint32_t slotb = sb + RINGOFF + (uint32_t)(s & 3) * 32768u + lane * 8;
            #pragma unroll
            for (int kgl = 0; kgl < 4; kgl++) {
                const uint32_t* aq = &qa[hf * 16 + kgl * 4];
                #pragma unroll
                for (int t = 0; t < 32; t++) {
                    uint32_t b0, b1;
                    asm volatile("ld.shared.v2.b32 {%0,%1}, [%2];"
                                 : "=r"(b0), "=r"(b1)
                                 : "r"(slotb + (kgl * 32 + t) * 256));
                    mma_s8(acc[t], aq, b0, b1);
                }
            }
        }

        // epilogue: dequant + bias + leaky
        const float c1 = aprev * (1.f / (127.f * 2032.f));
        float lmx = 0.f;
        #pragma unroll
        for (int t = 0; t < 32; t++) {
            float2 bb = *(const float2*)(sbias + (l << 8) + 8 * t + 2 * j);
            float v0 = fmaf((float)acc[t][0], c1, bb.x);
            float v1 = fmaf((float)acc[t][1], c1, bb.y);
            float v2 = fmaf((float)acc[t][2], c1, bb.x);
            float v3 = fmaf((float)acc[t][3], c1, bb.y);
            v0 = v0 >= 0.f ? v0 : 0.01f * v0;  v1 = v1 >= 0.f ? v1 : 0.01f * v1;
            v2 = v2 >= 0.f ? v2 : 0.01f * v2;  v3 = v3 >= 0.f ? v3 : 0.01f * v3;
            va[t][0] = v0; va[t][1] = v1; va[t][2] = v2; va[t][3] = v3;
            lmx = fmaxf(lmx, fmaxf(fmaxf(fabsf(v0), fabsf(v1)), fmaxf(fabsf(v2), fabsf(v3))));
        }
        if (l < 7) {
            #pragma unroll
            for (int o = 16; o; o >>= 1) lmx = fmaxf(lmx, __shfl_xor_sync(0xffffffffu, lmx, o));
            if (lane == 0) sred[warp] = lmx;
            __syncthreads();
            amax = sred[0];
            #pragma unroll
            for (int w = 1; w < 8; w++) amax = fmaxf(amax, sred[w]);
            quant_pack(va, amax > 0.f ? 127.f / amax : 0.f, qa, lane);
            aprev = amax;
        }
    }

    // ---- fused head: logits = h8 @ Wlast + blast, then log_softmax ----
    float a3[2][3] = {{0.f, 0.f, 0.f}, {0.f, 0.f, 0.f}};
    #pragma unroll
    for (int t = 0; t < 32; t++) {
        const int c0 = 8 * t + 2 * j;
        float w00 = sWl[c0 * 3 + 0], w01 = sWl[c0 * 3 + 1], w02 = sWl[c0 * 3 + 2];
        float w10 = sWl[c0 * 3 + 3], w11 = sWl[c0 * 3 + 4], w12 = sWl[c0 * 3 + 5];
        a3[0][0] += va[t][0] * w00 + va[t][1] * w10;
        a3[0][1] += va[t][0] * w01 + va[t][1] * w11;
        a3[0][2] += va[t][0] * w02 + va[t][1] * w12;
        a3[1][0] += va[t][2] * w00 + va[t][3] * w10;
        a3[1][1] += va[t][2] * w01 + va[t][3] * w11;
        a3[1][2] += va[t][2] * w02 + va[t][3] * w12;
    }
    #pragma unroll
    for (int off = 1; off <= 2; off <<= 1) {
        #pragma unroll
        for (int r = 0; r < 2; r++)
            #pragma unroll
            for (int c = 0; c < 3; c++)
                a3[r][c] += __shfl_xor_sync(0xffffffffu, a3[r][c], off);
    }
    if (j == 0) {
        const int g = lane >> 2;
        const float bb0 = sbl[0], bb1 = sbl[1], bb2 = sbl[2];
        #pragma unroll
        for (int r = 0; r < 2; r++) {
            size_t e = m0 + warp * 16 + g + 8 * r;
            float l0 = a3[r][0] + bb0, l1 = a3[r][1] + bb1, l2 = a3[r][2] + bb2;
            float m = fmaxf(l0, fmaxf(l1, l2));
            float ls = m + logf(expf(l0 - m) + expf(l1 - m) + expf(l2 - m));
            out[e * 3 + 0] = l0 - ls;
            out[e * 3 + 1] = l1 - ls;
            out[e * 3 + 2] = l2 - ls;
        }
    }
}

// ============================ host ============================
extern "C" void kernel_launch(void* const* d_in, const int* in_sizes, int n_in,
                              void* d_out, int out_size) {
    const float* x  = (const float*)d_in[0];
    const int*   ei = (const int*)d_in[1];
    const float* ea = (const float*)d_in[2];
    const float* Wx = (const float*)d_in[3];
    const float* bx = (const float*)d_in[4];
    const float* W0 = (const float*)d_in[5];
    const float* b0 = (const float*)d_in[6];
    const float* Wm = (const float*)d_in[7];
    const float* bm = (const float*)d_in[8];
    const float* Wl = (const float*)d_in[9];
    const float* bl = (const float*)d_in[10];
    float* out = (float*)d_out;

    void* p;
    cudaGetSymbolAddress(&p, g_xb);    __nv_bfloat16* xb    = (__nv_bfloat16*)p;
    cudaGetSymbolAddress(&p, g_hnode); __nv_bfloat16* hnode = (__nv_bfloat16*)p;
    cudaGetSymbolAddress(&p, g_grow);  __nv_bfloat16* grow  = (__nv_bfloat16*)p;
    cudaGetSymbolAddress(&p, g_gcol);  __nv_bfloat16* gcol  = (__nv_bfloat16*)p;
    cudaGetSymbolAddress(&p, g_h0);    __nv_bfloat16* h0p   = (__nv_bfloat16*)p;
    cudaGetSymbolAddress(&p, g_Bx);    __nv_bfloat16* Bx    = (__nv_bfloat16*)p;
    cudaGetSymbolAddress(&p, g_B0a);   __nv_bfloat16* B0a   = (__nv_bfloat16*)p;
    cudaGetSymbolAddress(&p, g_B0b);   __nv_bfloat16* B0b   = (__nv_bfloat16*)p;
    cudaGetSymbolAddress(&p, g_Bq);    uint2* Bq            = (uint2*)p;

    constexpr int SMEM = 65536;
    constexpr int FSMEM = 65536 + 131072 + 8192 + 3072 + 16 + 32;   // 207,936
    cudaFuncSetAttribute(gemm_mma<256, 128, true,  true >, cudaFuncAttributeMaxDynamicSharedMemorySize, SMEM);
    cudaFuncSetAttribute(gemm_mma<128, 256, false, false>, cudaFuncAttributeMaxDynamicSharedMemorySize, SMEM);
    cudaFuncSetAttribute(fused_mid_q, cudaFuncAttributeMaxDynamicSharedMemorySize, FSMEM);

    // 1: all prep (x->bf16, weight images bf16 + s8 fragment image, idx detect)
    prep_everything<<<8192, 256>>>(x, Wx, W0, Wm, (const unsigned*)ei);
    // 2: node MLP: h_node = leaky(x @ Wx + bx)
    gemm_mma<256, 128, true, true><<<dim3(NNODES / 128, 1), 256, SMEM>>>(xb, Bx, bx, hnode);
    // 3-4: node-level edge-GEMM precompute
    gemm_mma<128, 256, false, false><<<dim3(NNODES / 128, 2), 256, SMEM>>>(hnode, B0a, nullptr, grow);
    gemm_mma<128, 256, false, false><<<dim3(NNODES / 128, 2), 256, SMEM>>>(hnode, B0b, nullptr, gcol);
    // 5: gather + ea matvec + combine + leaky -> h0
    gather_combine_ea<<<NEDGES / 64, 256>>>(ei, ea, W0, b0, grow, gcol, h0p);
    // 6: fused int8 mids + head + log_softmax   (<- ncu capture target)
    fused_mid_q<<<NEDGES / 128, 256, FSMEM>>>(h0p, Bq, bm, Wl, bl, out);
}

// round 8
// speedup vs baseline: 2.2843x; 2.2843x over previous
#include <cuda_runtime.h>
#include <cuda_bf16.h>
#include <cstdint>

#define NNODES 65536
#define NEDGES 262144

// ============================ device scratch ============================
__device__ __align__(256) __nv_bfloat16 g_xb   [NNODES * 256];
__device__ __align__(256) __nv_bfloat16 g_hnode[NNODES * 128];
__device__ __align__(256) __nv_bfloat16 g_grow [NNODES * 256];
__device__ __align__(256) __nv_bfloat16 g_gcol [NNODES * 256];
__device__ __align__(256) __nv_bfloat16 g_h0   [(size_t)NEDGES * 256];
__device__ __align__(256) __nv_bfloat16 g_Bx [128 * 256];
__device__ __align__(256) __nv_bfloat16 g_B0a[256 * 128];
__device__ __align__(256) __nv_bfloat16 g_B0b[256 * 128];
__device__ __align__(256) __nv_bfloat16 g_Bm [8][256 * 256];
__device__ int g_idx64;

// ============================ PTX helpers (base PTX only) ============================
__device__ __forceinline__ uint32_t smem_u32(const void* p) {
    uint32_t a;
    asm("{ .reg .u64 t; cvta.to.shared.u64 t, %1; cvt.u32.u64 %0, t; }" : "=r"(a) : "l"(p));
    return a;
}
__device__ __forceinline__ void cp16(uint32_t dst, const void* src) {
    asm volatile("cp.async.cg.shared.global [%0], [%1], 16;" :: "r"(dst), "l"(src));
}
__device__ __forceinline__ void cp_commit() {
    asm volatile("cp.async.commit_group;" ::: "memory");
}
template <int N>
__device__ __forceinline__ void cp_wait() {
    asm volatile("cp.async.wait_group %0;" :: "n"(N) : "memory");
}
__device__ __forceinline__ void ldm_x4(uint32_t* r, uint32_t addr) {
    asm volatile("ldmatrix.sync.aligned.m8n8.x4.shared.b16 {%0,%1,%2,%3}, [%4];"
                 : "=r"(r[0]), "=r"(r[1]), "=r"(r[2]), "=r"(r[3]) : "r"(addr));
}
__device__ __forceinline__ void ldm_x2(uint32_t* r, uint32_t addr) {
    asm volatile("ldmatrix.sync.aligned.m8n8.x2.shared.b16 {%0,%1}, [%2];"
                 : "=r"(r[0]), "=r"(r[1]) : "r"(addr));
}
__device__ __forceinline__ void mma_bf16(float* c, const uint32_t* a, const uint32_t* b) {
    asm volatile(
        "mma.sync.aligned.m16n8k16.row.col.f32.bf16.bf16.f32 "
        "{%0,%1,%2,%3}, {%4,%5,%6,%7}, {%8,%9}, {%0,%1,%2,%3};"
        : "+f"(c[0]), "+f"(c[1]), "+f"(c[2]), "+f"(c[3])
        : "r"(a[0]), "r"(a[1]), "r"(a[2]), "r"(a[3]), "r"(b[0]), "r"(b[1]));
}

// ============================ prep kernels ============================
__global__ void detect_idx64(const unsigned* __restrict__ ei) {
    if (threadIdx.x == 0 && blockIdx.x == 0) {
        int is64 = 1;
        for (int i = 0; i < 512; i++)
            if (ei[2 * i + 1] != 0u) { is64 = 0; break; }
        g_idx64 = is64;
    }
}

__global__ void conv_f32_bf16(const float* __restrict__ src, __nv_bfloat16* __restrict__ dst, int n) {
    for (int i = blockIdx.x * blockDim.x + threadIdx.x; i < n; i += gridDim.x * blockDim.x)
        dst[i] = __float2bfloat16(src[i]);
}

// Coalesced transpose: W fp32 [row0+k][n] (ld=ldW) -> Bimg[n][k] bf16 (zero-pad k>=Ksrc).
__global__ void prep_Bt(const float* __restrict__ W, int row0, int ldW, int Ksrc, int Kpad,
                        size_t wlstride, size_t blstride, __nv_bfloat16* __restrict__ B) {
    __shared__ float tile[32][33];
    W += (size_t)blockIdx.z * wlstride;
    B += (size_t)blockIdx.z * blstride;
    const int n0 = blockIdx.x * 32, k0 = blockIdx.y * 32;
    const int tx = threadIdx.x, ty = threadIdx.y;
    #pragma unroll
    for (int r = 0; r < 32; r += 8) {
        int k = k0 + ty + r;
        tile[ty + r][tx] = (k < Ksrc) ? W[(size_t)(row0 + k) * ldW + n0 + tx] : 0.f;
    }
    __syncthreads();
    #pragma unroll
    for (int r = 0; r < 32; r += 8) {
        int n = n0 + ty + r;
        B[(size_t)n * Kpad + k0 + tx] = __float2bfloat16(tile[tx][ty + r]);
    }
}

// ============================ generic bf16 HMMA GEMM (prep stages) ============================
template <int K, int NOUT, bool LEAKY, bool HASBIAS, bool DUAL>
__global__ void __launch_bounds__(256)
gemm_mma(const __nv_bfloat16* __restrict__ A, const __nv_bfloat16* __restrict__ Bin,
         const __nv_bfloat16* __restrict__ B2, const float* __restrict__ bias,
         __nv_bfloat16* __restrict__ Out1, __nv_bfloat16* __restrict__ Out2) {
    static_assert(K % 64 == 0, "");
    constexpr int KT = K / 64;
    extern __shared__ char smem[];
    const uint32_t sb = smem_u32(smem);
    constexpr uint32_t STAGE = 32768, BOFF = 16384;

    const __nv_bfloat16* B = (DUAL && blockIdx.z) ? B2 : Bin;
    __nv_bfloat16* Out = (DUAL && blockIdx.z) ? Out2 : Out1;

    const int tid = threadIdx.x;
    const int lane = tid & 31, warp = tid >> 5;
    const int warp_m = warp & 1;
    const int warp_n = warp >> 1;
    const size_t m0 = (size_t)blockIdx.x * 128;
    const int n0 = blockIdx.y * 128;

    float acc[4][4][4];
    #pragma unroll
    for (int i = 0; i < 4; i++)
        #pragma unroll
        for (int j = 0; j < 4; j++)
            #pragma unroll
            for (int q = 0; q < 4; q++) acc[i][j][q] = 0.f;

    auto load_stage = [&](int stage, int kt) {
        const uint32_t base = sb + stage * STAGE;
        #pragma unroll
        for (int i = 0; i < 4; i++) {
            int idx = tid + i * 256;
            int r = idx >> 3, c8 = idx & 7;
            uint32_t dst = base + r * 128 + (((c8 ^ (r & 7))) << 4);
            cp16(dst, A + (m0 + r) * K + kt * 64 + c8 * 8);
        }
        #pragma unroll
        for (int i = 0; i < 4; i++) {
            int idx = tid + i * 256;
            int r = idx >> 3, c8 = idx & 7;
            uint32_t dst = base + BOFF + r * 128 + (((c8 ^ (r & 7))) << 4);
            cp16(dst, B + (size_t)(n0 + r) * K + kt * 64 + c8 * 8);
        }
    };

    load_stage(0, 0);
    cp_commit();

    for (int kt = 0; kt < KT; kt++) {
        if (kt + 1 < KT) { load_stage((kt + 1) & 1, kt + 1); cp_commit(); cp_wait<1>(); }
        else             { cp_wait<0>(); }
        __syncthreads();

        const uint32_t abase = sb + (kt & 1) * STAGE;
        const uint32_t bbase = abase + BOFF;
        #pragma unroll
        for (int ks = 0; ks < 4; ks++) {
            uint32_t af[4][4];
            #pragma unroll
            for (int mi = 0; mi < 4; mi++) {
                int r = warp_m * 64 + mi * 16 + (lane & 15);
                int c8 = ks * 2 + (lane >> 4);
                ldm_x4(af[mi], abase + r * 128 + ((c8 ^ (r & 7)) << 4));
            }
            uint32_t bf2[4][2];
            #pragma unroll
            for (int ni = 0; ni < 4; ni++) {
                int r = warp_n * 32 + ni * 8 + (lane & 7);
                int c8 = ks * 2 + ((lane >> 3) & 1);
                ldm_x2(bf2[ni], bbase + r * 128 + ((c8 ^ (r & 7)) << 4));
            }
            #pragma unroll
            for (int mi = 0; mi < 4; mi++)
                #pragma unroll
                for (int ni = 0; ni < 4; ni++)
                    mma_bf16(acc[mi][ni], af[mi], bf2[ni]);
        }
        __syncthreads();
    }

    const int g = lane >> 2;
    #pragma unroll
    for (int ni = 0; ni < 4; ni++) {
        const int col = n0 + warp_n * 32 + ni * 8 + ((lane & 3) << 1);
        float bb0 = 0.f, bb1 = 0.f;
        if (HASBIAS) { bb0 = __ldg(bias + col); bb1 = __ldg(bias + col + 1); }
        #pragma unroll
        for (int mi = 0; mi < 4; mi++) {
            const size_t r0 = m0 + warp_m * 64 + mi * 16 + g;
            float v0 = acc[mi][ni][0] + bb0, v1 = acc[mi][ni][1] + bb1;
            float v2 = acc[mi][ni][2] + bb0, v3 = acc[mi][ni][3] + bb1;
            if (LEAKY) {
                v0 = v0 >= 0.f ? v0 : 0.01f * v0;  v1 = v1 >= 0.f ? v1 : 0.01f * v1;
                v2 = v2 >= 0.f ? v2 : 0.01f * v2;  v3 = v3 >= 0.f ? v3 : 0.01f * v3;
            }
            __nv_bfloat162 p0 = __floats2bfloat162_rn(v0, v1);
            __nv_bfloat162 p1 = __floats2bfloat162_rn(v2, v3);
            *(uint32_t*)(Out + r0 * NOUT + col)       = *(uint32_t*)&p0;
            *(uint32_t*)(Out + (r0 + 8) * NOUT + col) = *(uint32_t*)&p1;
        }
    }
}

// ============================ gather + ea-matvec + combine ============================
__global__ void __launch_bounds__(256)
gather_combine_ea(const int* __restrict__ ei, const float* __restrict__ ea,
                  const float* __restrict__ W0, const float* __restrict__ b0,
                  const __nv_bfloat16* __restrict__ gr, const __nv_bfloat16* __restrict__ gc,
                  __nv_bfloat16* __restrict__ h0) {
    __shared__ float sea[64][16];
    __shared__ int srow[64], scol[64];
    const int t = threadIdx.x;
    const long e0 = (long)blockIdx.x * 64;
    const int is64 = g_idx64;
    if (t < 64) {
        long e = e0 + t;
        if (is64) { srow[t] = ei[2 * e]; scol[t] = ei[2 * (NEDGES + e)]; }
        else      { srow[t] = ei[e];     scol[t] = ei[NEDGES + e]; }
    }
    {
        int e = t >> 2, k = (t & 3) * 4;
        *(float4*)&sea[e][k] = *(const float4*)(ea + (e0 + e) * 16 + k);
    }
    const int cp = t & 127;
    float2 w[16];
    #pragma unroll
    for (int k = 0; k < 16; k++)
        w[k] = *(const float2*)(W0 + (size_t)(256 + k) * 256 + 2 * cp);
    const float2 bb = *(const float2*)(b0 + 2 * cp);
    __syncthreads();

    const int eo = t >> 7;
    for (int i = eo; i < 64; i += 2) {
        float v0 = bb.x, v1 = bb.y;
        #pragma unroll
        for (int k = 0; k < 16; k++) {
            float s = sea[i][k];
            v0 += s * w[k].x;
            v1 += s * w[k].y;
        }
        const __nv_bfloat162 gv = ((const __nv_bfloat162*)(gr + (size_t)srow[i] * 256))[cp];
        const __nv_bfloat162 cv = ((const __nv_bfloat162*)(gc + (size_t)scol[i] * 256))[cp];
        float2 gb = __bfloat1622float2(gv);
        float2 cb = __bfloat1622float2(cv);
        v0 += gb.x + cb.x;
        v1 += gb.y + cb.y;
        v0 = v0 >= 0.f ? v0 : 0.01f * v0;
        v1 = v1 >= 0.f ? v1 : 0.01f * v1;
        ((__nv_bfloat162*)(h0 + (size_t)(e0 + i) * 256))[cp] = __floats2bfloat162_rn(v0, v1);
    }
}

// ============================ fused 8 mid layers + head (2-phase / N-half slots) ============================
// CTA = 128 edges, 8 warps x 16-row tiles, activations chained in registers.
// Ring: 3 x 64KB regions; slot s (0..15) = (layer s>>1, N-half s&1) = [128 N rows][256 K] bf16,
// row pitch 512B. Only 2 sync points per layer. A-tile stages through ring region 2.
__global__ void __launch_bounds__(256, 1)
fused_mid(const __nv_bfloat16* __restrict__ h0, const __nv_bfloat16* __restrict__ Bm,
          const float* __restrict__ bm, const float* __restrict__ Wl,
          const float* __restrict__ bl, float* __restrict__ out) {
    extern __shared__ char smem[];
    const uint32_t sb = smem_u32(smem);
    constexpr uint32_t PARAM = 196608;                  // ring 3 x 64KB at [0, 192K)
    float* sbias = (float*)(smem + PARAM);              // 8 x 256 fp32
    float* sWl   = (float*)(smem + PARAM + 8192);       // 256 x 3 fp32
    float* sbl   = (float*)(smem + PARAM + 8192 + 3072);

    const int tid = threadIdx.x, lane = tid & 31, warp = tid >> 5;
    const size_t m0 = (size_t)blockIdx.x * 128;

    for (int i = tid; i < 2048; i += 256) sbias[i] = bm[i];
    for (int i = tid; i < 768; i += 256) sWl[i] = Wl[i];
    if (tid < 3) sbl[tid] = bl[tid];

    // slot s -> ring region s%3; slot source = Bm + s*32768 (N-half-contiguous image)
    auto loadSlot = [&](int s) {
        const uint32_t base = sb + (uint32_t)(s % 3) * 65536u;
        const __nv_bfloat16* src = Bm + (size_t)s * 32768;
        #pragma unroll
        for (int i = 0; i < 16; i++) {
            int idx = tid + i * 256;            // 0..4095 16B units
            int r = idx >> 5, u = idx & 31;     // r: local N row 0..127, u: unit in 512B row
            int kc = u >> 3, c8 = u & 7;
            cp16(base + r * 512 + kc * 128 + ((c8 ^ (r & 7)) << 4),
                 src + (size_t)r * 256 + u * 8);
        }
    };

    // A tile (h0, 128x256 bf16 = 64KB) -> ring region 2 as 4 chunks of [128][64], 128B pitch
    #pragma unroll
    for (int i = 0; i < 16; i++) {
        int idx = tid + i * 256;
        int r = idx >> 5, u = idx & 31;
        int kc = u >> 3, c8 = u & 7;
        cp16(sb + 131072 + kc * 16384 + r * 128 + ((c8 ^ (r & 7)) << 4),
             h0 + (m0 + r) * 256 + u * 8);
    }
    cp_commit();                 // G0 = A
    loadSlot(0); cp_commit();    // G1 (region 0)
    loadSlot(1); cp_commit();    // G2 (region 1)
    cp_wait<2>();                // A ready
    __syncthreads();

    // ldmatrix A -> packed activation fragments pA[32][2]
    uint32_t pA[32][2], pB[32][2];
    #pragma unroll
    for (int s = 0; s < 16; s++) {
        int rr = warp * 16 + (lane & 15);
        int cc = (s & 3) * 2 + (lane >> 4);
        uint32_t f[4];
        ldm_x4(f, sb + 131072 + (s >> 2) * 16384 + rr * 128 + ((cc ^ (rr & 7)) << 4));
        pA[2 * s][0] = f[0]; pA[2 * s][1] = f[1];
        pA[2 * s + 1][0] = f[2]; pA[2 * s + 1][1] = f[3];
    }
    __syncthreads();             // region 2 free (A consumed by all warps)

    const int j = lane & 3;
    const int rr_lo = ((lane >> 4) << 3) + (lane & 7);

    // one phase: slot s = 2l+h covers n-tiles 16h..16h+15 with full K
    auto do_phase = [&](int l, int h, uint32_t (&src)[32][2], uint32_t (&dst)[32][2]) {
        const int s = 2 * l + h;
        cp_wait<1>();
        __syncthreads();
        if (s + 2 < 16) loadSlot(s + 2);
        cp_commit();
        const uint32_t slotb = sb + (uint32_t)(s % 3) * 65536u;

        float acc[16][4];
        #pragma unroll
        for (int q = 0; q < 16; q++) {
            float2 bb = *(const float2*)(sbias + (l << 8) + (h << 7) + 8 * q + 2 * j);
            acc[q][0] = bb.x; acc[q][1] = bb.y; acc[q][2] = bb.x; acc[q][3] = bb.y;
        }
        #pragma unroll
        for (int kh = 0; kh < 4; kh++) {
            #pragma unroll
            for (int ksl = 0; ksl < 4; ksl++) {
                const int ai = kh * 8 + ksl * 2;
                uint32_t a[4] = {src[ai][0], src[ai][1], src[ai + 1][0], src[ai + 1][1]};
                const int cc = ksl * 2 + ((lane >> 3) & 1);
                #pragma unroll
                for (int np = 0; np < 8; np++) {
                    int rr = np * 16 + rr_lo;
                    uint32_t bf[4];
                    ldm_x4(bf, slotb + rr * 512 + kh * 128 + ((cc ^ (rr & 7)) << 4));
                    mma_bf16(acc[np * 2], a, bf);
                    mma_bf16(acc[np * 2 + 1], a, bf + 2);
                }
            }
        }
        // leaky + pack into destination activation fragments
        #pragma unroll
        for (int q = 0; q < 16; q++) {
            float v0 = acc[q][0], v1 = acc[q][1], v2 = acc[q][2], v3 = acc[q][3];
            v0 = v0 >= 0.f ? v0 : 0.01f * v0;  v1 = v1 >= 0.f ? v1 : 0.01f * v1;
            v2 = v2 >= 0.f ? v2 : 0.01f * v2;  v3 = v3 >= 0.f ? v3 : 0.01f * v3;
            __nv_bfloat162 p0 = __floats2bfloat162_rn(v0, v1);
            __nv_bfloat162 p1 = __floats2bfloat162_rn(v2, v3);
            dst[16 * h + q][0] = *(uint32_t*)&p0;
            dst[16 * h + q][1] = *(uint32_t*)&p1;
        }
    };
    auto do_layer = [&](int l, uint32_t (&src)[32][2], uint32_t (&dst)[32][2]) {
        do_phase(l, 0, src, dst);
        do_phase(l, 1, src, dst);
    };
    do_layer(0, pA, pB);
    do_layer(1, pB, pA);
    do_layer(2, pA, pB);
    do_layer(3, pB, pA);
    do_layer(4, pA, pB);
    do_layer(5, pB, pA);
    do_layer(6, pA, pB);
    do_layer(7, pB, pA);

    // ---- fused head: logits = h8 @ Wlast + blast, then log_softmax ----
    float a3[2][3] = {{0.f, 0.f, 0.f}, {0.f, 0.f, 0.f}};
    #pragma unroll
    for (int t = 0; t < 32; t++) {
        float2 x = __bfloat1622float2(*(__nv_bfloat162*)&pA[t][0]);
        float2 y = __bfloat1622float2(*(__nv_bfloat162*)&pA[t][1]);
        const int c0 = 8 * t + 2 * j;
        float w00 = sWl[c0 * 3 + 0], w01 = sWl[c0 * 3 + 1], w02 = sWl[c0 * 3 + 2];
        float w10 = sWl[c0 * 3 + 3], w11 = sWl[c0 * 3 + 4], w12 = sWl[c0 * 3 + 5];
        a3[0][0] += x.x * w00 + x.y * w10;
        a3[0][1] += x.x * w01 + x.y * w11;
        a3[0][2] += x.x * w02 + x.y * w12;
        a3[1][0] += y.x * w00 + y.y * w10;
        a3[1][1] += y.x * w01 + y.y * w11;
        a3[1][2] += y.x * w02 + y.y * w12;
    }
    #pragma unroll
    for (int off = 1; off <= 2; off <<= 1) {
        #pragma unroll
        for (int r = 0; r < 2; r++)
            #pragma unroll
            for (int c = 0; c < 3; c++)
                a3[r][c] += __shfl_xor_sync(0xffffffffu, a3[r][c], off);
    }
    if (j == 0) {
        const int g = lane >> 2;
        const float bb0 = sbl[0], bb1 = sbl[1], bb2 = sbl[2];
        #pragma unroll
        for (int r = 0; r < 2; r++) {
            size_t e = m0 + warp * 16 + g + 8 * r;
            float l0 = a3[r][0] + bb0, l1 = a3[r][1] + bb1, l2 = a3[r][2] + bb2;
            float m = fmaxf(l0, fmaxf(l1, l2));
            float ls = m + logf(expf(l0 - m) + expf(l1 - m) + expf(l2 - m));
            out[e * 3 + 0] = l0 - ls;
            out[e * 3 + 1] = l1 - ls;
            out[e * 3 + 2] = l2 - ls;
        }
    }
}

// ============================ host ============================
extern "C" void kernel_launch(void* const* d_in, const int* in_sizes, int n_in,
                              void* d_out, int out_size) {
    const float* x  = (const float*)d_in[0];
    const int*   ei = (const int*)d_in[1];
    const float* ea = (const float*)d_in[2];
    const float* Wx = (const float*)d_in[3];
    const float* bx = (const float*)d_in[4];
    const float* W0 = (const float*)d_in[5];
    const float* b0 = (const float*)d_in[6];
    const float* Wm = (const float*)d_in[7];
    const float* bm = (const float*)d_in[8];
    const float* Wl = (const float*)d_in[9];
    const float* bl = (const float*)d_in[10];
    float* out = (float*)d_out;

    void* p;
    cudaGetSymbolAddress(&p, g_xb);    __nv_bfloat16* xb    = (__nv_bfloat16*)p;
    cudaGetSymbolAddress(&p, g_hnode); __nv_bfloat16* hnode = (__nv_bfloat16*)p;
    cudaGetSymbolAddress(&p, g_grow);  __nv_bfloat16* grow  = (__nv_bfloat16*)p;
    cudaGetSymbolAddress(&p, g_gcol);  __nv_bfloat16* gcol  = (__nv_bfloat16*)p;
    cudaGetSymbolAddress(&p, g_h0);    __nv_bfloat16* h0p   = (__nv_bfloat16*)p;
    cudaGetSymbolAddress(&p, g_Bx);    __nv_bfloat16* Bx    = (__nv_bfloat16*)p;
    cudaGetSymbolAddress(&p, g_B0a);   __nv_bfloat16* B0a   = (__nv_bfloat16*)p;
    cudaGetSymbolAddress(&p, g_B0b);   __nv_bfloat16* B0b   = (__nv_bfloat16*)p;
    cudaGetSymbolAddress(&p, g_Bm);    __nv_bfloat16* Bm    = (__nv_bfloat16*)p;

    constexpr int SMEM = 65536;
    constexpr int FSMEM = 196608 + 8192 + 3072 + 16;   // 207,888
    cudaFuncSetAttribute(gemm_mma<256, 128, true,  true,  false>, cudaFuncAttributeMaxDynamicSharedMemorySize, SMEM);
    cudaFuncSetAttribute(gemm_mma<128, 256, false, false, true >, cudaFuncAttributeMaxDynamicSharedMemorySize, SMEM);
    cudaFuncSetAttribute(fused_mid, cudaFuncAttributeMaxDynamicSharedMemorySize, FSMEM);

    // --- prep ---
    detect_idx64<<<1, 32>>>((const unsigned*)ei);
    conv_f32_bf16<<<4096, 256>>>(x, xb, NNODES * 256);
    prep_Bt<<<dim3(4, 8, 1), dim3(32, 8)>>>(Wx, 0, 128, 256, 256, 0, 0, Bx);
    prep_Bt<<<dim3(8, 4, 1), dim3(32, 8)>>>(W0, 0,   256, 128, 128, 0, 0, B0a);
    prep_Bt<<<dim3(8, 4, 1), dim3(32, 8)>>>(W0, 128, 256, 128, 128, 0, 0, B0b);
    prep_Bt<<<dim3(8, 8, 8), dim3(32, 8)>>>(Wm, 0, 256, 256, 256, 65536, 65536, Bm);

    // --- node MLP: h_node = leaky(x @ Wx + bx) ---
    gemm_mma<256, 128, true, true, false><<<dim3(NNODES / 128, 1, 1), 256, SMEM>>>(
        xb, Bx, nullptr, bx, hnode, nullptr);
    // --- node-level edge-GEMM precompute: grow/gcol in one dual launch ---
    gemm_mma<128, 256, false, false, true><<<dim3(NNODES / 128, 2, 2), 256, SMEM>>>(
        hnode, B0a, B0b, nullptr, grow, gcol);
    // --- gather + ea matvec + combine + leaky -> h0 ---
    gather_combine_ea<<<NEDGES / 64, 256>>>(ei, ea, W0, b0, grow, gcol, h0p);
    // --- fused: 8 hidden layers + head + log_softmax ---
    fused_mid<<<NEDGES / 128, 256, FSMEM>>>(h0p, Bm, bm, Wl, bl, out);
}

// round 9
// speedup vs baseline: 2.5655x; 1.1231x over previous
#include <cuda_runtime.h>
#include <cuda_bf16.h>
#include <cstdint>

#define NNODES 65536
#define NEDGES 262144

// ============================ device scratch ============================
__device__ __align__(256) __nv_bfloat16 g_xb   [NNODES * 256];
__device__ __align__(256) __nv_bfloat16 g_hnode[NNODES * 128];
__device__ __align__(256) __nv_bfloat16 g_grow [NNODES * 256];
__device__ __align__(256) __nv_bfloat16 g_gcol [NNODES * 256];
__device__ __align__(256) __nv_bfloat16 g_h0   [(size_t)NEDGES * 256];
__device__ __align__(256) __nv_bfloat16 g_Bx [128 * 256];
__device__ __align__(256) __nv_bfloat16 g_B0a[256 * 128];
__device__ __align__(256) __nv_bfloat16 g_B0b[256 * 128];
__device__ __align__(256) __nv_bfloat16 g_Bm [8][256 * 256];
__device__ int g_idx64;

// ============================ PTX helpers (base PTX only) ============================
__device__ __forceinline__ uint32_t smem_u32(const void* p) {
    uint32_t a;
    asm("{ .reg .u64 t; cvta.to.shared.u64 t, %1; cvt.u32.u64 %0, t; }" : "=r"(a) : "l"(p));
    return a;
}
__device__ __forceinline__ void cp16(uint32_t dst, const void* src) {
    asm volatile("cp.async.cg.shared.global [%0], [%1], 16;" :: "r"(dst), "l"(src));
}
__device__ __forceinline__ void cp_commit() {
    asm volatile("cp.async.commit_group;" ::: "memory");
}
template <int N>
__device__ __forceinline__ void cp_wait() {
    asm volatile("cp.async.wait_group %0;" :: "n"(N) : "memory");
}
__device__ __forceinline__ void ldm_x4(uint32_t* r, uint32_t addr) {
    asm volatile("ldmatrix.sync.aligned.m8n8.x4.shared.b16 {%0,%1,%2,%3}, [%4];"
                 : "=r"(r[0]), "=r"(r[1]), "=r"(r[2]), "=r"(r[3]) : "r"(addr));
}
__device__ __forceinline__ void ldm_x2(uint32_t* r, uint32_t addr) {
    asm volatile("ldmatrix.sync.aligned.m8n8.x2.shared.b16 {%0,%1}, [%2];"
                 : "=r"(r[0]), "=r"(r[1]) : "r"(addr));
}
__device__ __forceinline__ void mma_bf16(float* c, const uint32_t* a, const uint32_t* b) {
    asm volatile(
        "mma.sync.aligned.m16n8k16.row.col.f32.bf16.bf16.f32 "
        "{%0,%1,%2,%3}, {%4,%5,%6,%7}, {%8,%9}, {%0,%1,%2,%3};"
        : "+f"(c[0]), "+f"(c[1]), "+f"(c[2]), "+f"(c[3])
        : "r"(a[0]), "r"(a[1]), "r"(a[2]), "r"(a[3]), "r"(b[0]), "r"(b[1]));
}

// ============================ prep kernels ============================
__global__ void detect_idx64(const unsigned* __restrict__ ei) {
    if (threadIdx.x == 0 && blockIdx.x == 0) {
        int is64 = 1;
        for (int i = 0; i < 512; i++)
            if (ei[2 * i + 1] != 0u) { is64 = 0; break; }
        g_idx64 = is64;
    }
}

__global__ void conv_f32_bf16(const float* __restrict__ src, __nv_bfloat16* __restrict__ dst, int n) {
    for (int i = blockIdx.x * blockDim.x + threadIdx.x; i < n; i += gridDim.x * blockDim.x)
        dst[i] = __float2bfloat16(src[i]);
}

// Coalesced transpose: W fp32 [row0+k][n] (ld=ldW) -> Bimg[n][k] bf16 (zero-pad k>=Ksrc).
__global__ void prep_Bt(const float* __restrict__ W, int row0, int ldW, int Ksrc, int Kpad,
                        size_t wlstride, size_t blstride, __nv_bfloat16* __restrict__ B) {
    __shared__ float tile[32][33];
    W += (size_t)blockIdx.z * wlstride;
    B += (size_t)blockIdx.z * blstride;
    const int n0 = blockIdx.x * 32, k0 = blockIdx.y * 32;
    const int tx = threadIdx.x, ty = threadIdx.y;
    #pragma unroll
    for (int r = 0; r < 32; r += 8) {
        int k = k0 + ty + r;
        tile[ty + r][tx] = (k < Ksrc) ? W[(size_t)(row0 + k) * ldW + n0 + tx] : 0.f;
    }
    __syncthreads();
    #pragma unroll
    for (int r = 0; r < 32; r += 8) {
        int n = n0 + ty + r;
        B[(size_t)n * Kpad + k0 + tx] = __float2bfloat16(tile[tx][ty + r]);
    }
}

// ============================ generic bf16 HMMA GEMM (prep stages) ============================
template <int K, int NOUT, bool LEAKY, bool HASBIAS, bool DUAL>
__global__ void __launch_bounds__(256)
gemm_mma(const __nv_bfloat16* __restrict__ A, const __nv_bfloat16* __restrict__ Bin,
         const __nv_bfloat16* __restrict__ B2, const float* __restrict__ bias,
         __nv_bfloat16* __restrict__ Out1, __nv_bfloat16* __restrict__ Out2) {
    static_assert(K % 64 == 0, "");
    constexpr int KT = K / 64;
    extern __shared__ char smem[];
    const uint32_t sb = smem_u32(smem);
    constexpr uint32_t STAGE = 32768, BOFF = 16384;

    const __nv_bfloat16* B = (DUAL && blockIdx.z) ? B2 : Bin;
    __nv_bfloat16* Out = (DUAL && blockIdx.z) ? Out2 : Out1;

    const int tid = threadIdx.x;
    const int lane = tid & 31, warp = tid >> 5;
    const int warp_m = warp & 1;
    const int warp_n = warp >> 1;
    const size_t m0 = (size_t)blockIdx.x * 128;
    const int n0 = blockIdx.y * 128;

    float acc[4][4][4];
    #pragma unroll
    for (int i = 0; i < 4; i++)
        #pragma unroll
        for (int j = 0; j < 4; j++)
            #pragma unroll
            for (int q = 0; q < 4; q++) acc[i][j][q] = 0.f;

    auto load_stage = [&](int stage, int kt) {
        const uint32_t base = sb + stage * STAGE;
        #pragma unroll
        for (int i = 0; i < 4; i++) {
            int idx = tid + i * 256;
            int r = idx >> 3, c8 = idx & 7;
            uint32_t dst = base + r * 128 + (((c8 ^ (r & 7))) << 4);
            cp16(dst, A + (m0 + r) * K + kt * 64 + c8 * 8);
        }
        #pragma unroll
        for (int i = 0; i < 4; i++) {
            int idx = tid + i * 256;
            int r = idx >> 3, c8 = idx & 7;
            uint32_t dst = base + BOFF + r * 128 + (((c8 ^ (r & 7))) << 4);
            cp16(dst, B + (size_t)(n0 + r) * K + kt * 64 + c8 * 8);
        }
    };

    load_stage(0, 0);
    cp_commit();

    for (int kt = 0; kt < KT; kt++) {
        if (kt + 1 < KT) { load_stage((kt + 1) & 1, kt + 1); cp_commit(); cp_wait<1>(); }
        else             { cp_wait<0>(); }
        __syncthreads();

        const uint32_t abase = sb + (kt & 1) * STAGE;
        const uint32_t bbase = abase + BOFF;
        #pragma unroll
        for (int ks = 0; ks < 4; ks++) {
            uint32_t af[4][4];
            #pragma unroll
            for (int mi = 0; mi < 4; mi++) {
                int r = warp_m * 64 + mi * 16 + (lane & 15);
                int c8 = ks * 2 + (lane >> 4);
                ldm_x4(af[mi], abase + r * 128 + ((c8 ^ (r & 7)) << 4));
            }
            uint32_t bf2[4][2];
            #pragma unroll
            for (int ni = 0; ni < 4; ni++) {
                int r = warp_n * 32 + ni * 8 + (lane & 7);
                int c8 = ks * 2 + ((lane >> 3) & 1);
                ldm_x2(bf2[ni], bbase + r * 128 + ((c8 ^ (r & 7)) << 4));
            }
            #pragma unroll
            for (int mi = 0; mi < 4; mi++)
                #pragma unroll
                for (int ni = 0; ni < 4; ni++)
                    mma_bf16(acc[mi][ni], af[mi], bf2[ni]);
        }
        __syncthreads();
    }

    const int g = lane >> 2;
    #pragma unroll
    for (int ni = 0; ni < 4; ni++) {
        const int col = n0 + warp_n * 32 + ni * 8 + ((lane & 3) << 1);
        float bb0 = 0.f, bb1 = 0.f;
        if (HASBIAS) { bb0 = __ldg(bias + col); bb1 = __ldg(bias + col + 1); }
        #pragma unroll
        for (int mi = 0; mi < 4; mi++) {
            const size_t r0 = m0 + warp_m * 64 + mi * 16 + g;
            float v0 = acc[mi][ni][0] + bb0, v1 = acc[mi][ni][1] + bb1;
            float v2 = acc[mi][ni][2] + bb0, v3 = acc[mi][ni][3] + bb1;
            if (LEAKY) {
                v0 = v0 >= 0.f ? v0 : 0.01f * v0;  v1 = v1 >= 0.f ? v1 : 0.01f * v1;
                v2 = v2 >= 0.f ? v2 : 0.01f * v2;  v3 = v3 >= 0.f ? v3 : 0.01f * v3;
            }
            __nv_bfloat162 p0 = __floats2bfloat162_rn(v0, v1);
            __nv_bfloat162 p1 = __floats2bfloat162_rn(v2, v3);
            *(uint32_t*)(Out + r0 * NOUT + col)       = *(uint32_t*)&p0;
            *(uint32_t*)(Out + (r0 + 8) * NOUT + col) = *(uint32_t*)&p1;
        }
    }
}

// ============================ gather + ea-matvec + combine ============================
__global__ void __launch_bounds__(256)
gather_combine_ea(const int* __restrict__ ei, const float* __restrict__ ea,
                  const float* __restrict__ W0, const float* __restrict__ b0,
                  const __nv_bfloat16* __restrict__ gr, const __nv_bfloat16* __restrict__ gc,
                  __nv_bfloat16* __restrict__ h0) {
    __shared__ float sea[64][16];
    __shared__ int srow[64], scol[64];
    const int t = threadIdx.x;
    const long e0 = (long)blockIdx.x * 64;
    const int is64 = g_idx64;
    if (t < 64) {
        long e = e0 + t;
        if (is64) { srow[t] = ei[2 * e]; scol[t] = ei[2 * (NEDGES + e)]; }
        else      { srow[t] = ei[e];     scol[t] = ei[NEDGES + e]; }
    }
    {
        int e = t >> 2, k = (t & 3) * 4;
        *(float4*)&sea[e][k] = *(const float4*)(ea + (e0 + e) * 16 + k);
    }
    const int cp = t & 127;
    float2 w[16];
    #pragma unroll
    for (int k = 0; k < 16; k++)
        w[k] = *(const float2*)(W0 + (size_t)(256 + k) * 256 + 2 * cp);
    const float2 bb = *(const float2*)(b0 + 2 * cp);
    __syncthreads();

    const int eo = t >> 7;
    for (int i = eo; i < 64; i += 2) {
        float v0 = bb.x, v1 = bb.y;
        #pragma unroll
        for (int k = 0; k < 16; k++) {
            float s = sea[i][k];
            v0 += s * w[k].x;
            v1 += s * w[k].y;
        }
        const __nv_bfloat162 gv = ((const __nv_bfloat162*)(gr + (size_t)srow[i] * 256))[cp];
        const __nv_bfloat162 cv = ((const __nv_bfloat162*)(gc + (size_t)scol[i] * 256))[cp];
        float2 gb = __bfloat1622float2(gv);
        float2 cb = __bfloat1622float2(cv);
        v0 += gb.x + cb.x;
        v1 += gb.y + cb.y;
        v0 = v0 >= 0.f ? v0 : 0.01f * v0;
        v1 = v1 >= 0.f ? v1 : 0.01f * v1;
        ((__nv_bfloat162*)(h0 + (size_t)(e0 + i) * 256))[cp] = __floats2bfloat162_rn(v0, v1);
    }
}

// ============================ fused 8 mid layers + head (warp-M=32, SMEM activations) ============================
// CTA = 128 edges. 8 warps in 4(M)x2(N) grid: warp owns 32 edges x 128 cols.
// Activations live in SMEM A region [0,64KB) (4 chunks [128][64], XOR swizzle);
// each layer LDSMs A per K-slice, MMAs against the R6-style 4x32KB K-quarter weight ring,
// then epilogue STSes leaky'd bf16 C back into the A region.
// Crossbar per CTA-layer: B 512KB + A 128KB + C 64KB = 704KB (vs 1MB at warp-M=16).
__global__ void __launch_bounds__(256, 1)
fused_mid(const __nv_bfloat16* __restrict__ h0, const __nv_bfloat16* __restrict__ Bm,
          const float* __restrict__ bm, const float* __restrict__ Wl,
          const float* __restrict__ bl, float* __restrict__ out) {
    extern __shared__ char smem[];
    const uint32_t sb = smem_u32(smem);
    constexpr uint32_t RINGOFF = 65536;               // ring: 4 x 32KB at [64K, 192K)
    constexpr uint32_t PARAM = 65536 + 131072;
    float* sbias = (float*)(smem + PARAM);            // 8 x 256 fp32
    float* sWl   = (float*)(smem + PARAM + 8192);     // 256 x 3 fp32
    float* sbl   = (float*)(smem + PARAM + 8192 + 3072);

    const int tid = threadIdx.x, lane = tid & 31, warp = tid >> 5;
    const int warp_m = warp >> 1;                     // 0..3 -> M offset *32
    const int warp_n = warp & 1;                      // 0..1 -> N offset *128
    const size_t m0 = (size_t)blockIdx.x * 128;

    for (int i = tid; i < 2048; i += 256) sbias[i] = bm[i];
    for (int i = tid; i < 768; i += 256) sWl[i] = Wl[i];
    if (tid < 3) sbl[tid] = bl[tid];

    // B ring loader (identical to R6): slot s -> layer s>>2, K-quarter s&3, region s&3
    auto loadB = [&](int s) {
        const uint32_t base = sb + RINGOFF + (uint32_t)(s & 3) * 32768u;
        const __nv_bfloat16* src = Bm + (size_t)(s >> 2) * 65536 + (s & 3) * 64;
        #pragma unroll
        for (int i = 0; i < 8; i++) {
            int idx = tid + i * 256;
            int r = idx >> 3, c8 = idx & 7;
            cp16(base + r * 128 + ((c8 ^ (r & 7)) << 4), src + (size_t)r * 256 + c8 * 8);
        }
    };
    loadB(0); cp_commit();
    loadB(1); cp_commit();

    // A tile (h0, 128x256) -> A region as 4 chunks of [128][64], XOR swizzle
    #pragma unroll
    for (int kc = 0; kc < 4; kc++)
        #pragma unroll
        for (int i = 0; i < 4; i++) {
            int idx = tid + i * 256;
            int r = idx >> 3, c8 = idx & 7;
            cp16(sb + kc * 16384 + r * 128 + ((c8 ^ (r & 7)) << 4),
                 h0 + (m0 + r) * 256 + kc * 64 + c8 * 8);
        }
    cp_commit();
    cp_wait<0>();
    __syncthreads();

    const int g = lane >> 2, j = lane & 3;
    const int rr_lo = ((lane >> 4) << 3) + (lane & 7);
    const int ar_lo = warp_m * 32 + (lane & 15);

    for (int l = 0; l < 8; ++l) {
        float acc[2][16][4];
        #pragma unroll
        for (int nt = 0; nt < 16; nt++) {
            float2 bb = *(const float2*)(sbias + (l << 8) + warp_n * 128 + 8 * nt + 2 * j);
            #pragma unroll
            for (int mi = 0; mi < 2; mi++) {
                acc[mi][nt][0] = bb.x; acc[mi][nt][1] = bb.y;
                acc[mi][nt][2] = bb.x; acc[mi][nt][3] = bb.y;
            }
        }
        #pragma unroll
        for (int kh = 0; kh < 4; kh++) {
            const int s = l * 4 + kh;
            cp_wait<1>();
            __syncthreads();
            if (s + 2 < 32) loadB(s + 2);
            cp_commit();
            const uint32_t bbase = sb + RINGOFF + (uint32_t)(s & 3) * 32768u;
            const uint32_t achk = sb + kh * 16384;
            #pragma unroll
            for (int ksl = 0; ksl < 4; ksl++) {
                // A frags: rows warp_m*32 + [0,16) and [16,32), k-slice ksl*16
                const int cca = ksl * 2 + (lane >> 4);
                uint32_t a0[4], a1[4];
                int r0 = ar_lo;
                ldm_x4(a0, achk + r0 * 128 + ((cca ^ (r0 & 7)) << 4));
                int r1 = ar_lo + 16;
                ldm_x4(a1, achk + r1 * 128 + ((cca ^ (r1 & 7)) << 4));
                const int ccb = ksl * 2 + ((lane >> 3) & 1);
                #pragma unroll
                for (int bt = 0; bt < 8; bt++) {
                    int rr = warp_n * 128 + bt * 16 + rr_lo;
                    uint32_t bf[4];
                    ldm_x4(bf, bbase + rr * 128 + ((ccb ^ (rr & 7)) << 4));
                    mma_bf16(acc[0][2 * bt],     a0, bf);
                    mma_bf16(acc[0][2 * bt + 1], a0, bf + 2);
                    mma_bf16(acc[1][2 * bt],     a1, bf);
                    mma_bf16(acc[1][2 * bt + 1], a1, bf + 2);
                }
            }
        }
        __syncthreads();   // all A reads of this layer complete before overwrite
        // epilogue: leaky + bf16 + STS back into A region
        #pragma unroll
        for (int mi = 0; mi < 2; mi++) {
            const int r  = warp_m * 32 + mi * 16 + g;
            const int r2 = r + 8;
            #pragma unroll
            for (int nt = 0; nt < 16; nt++) {
                float v0 = acc[mi][nt][0], v1 = acc[mi][nt][1];
                float v2 = acc[mi][nt][2], v3 = acc[mi][nt][3];
                v0 = v0 >= 0.f ? v0 : 0.01f * v0;  v1 = v1 >= 0.f ? v1 : 0.01f * v1;
                v2 = v2 >= 0.f ? v2 : 0.01f * v2;  v3 = v3 >= 0.f ? v3 : 0.01f * v3;
                __nv_bfloat162 p0 = __floats2bfloat162_rn(v0, v1);
                __nv_bfloat162 p1 = __floats2bfloat162_rn(v2, v3);
                const int c = warp_n * 128 + nt * 8;        // + 2j handled via byte offset
                const int kc = c >> 6, c8s = (c >> 3) & 7;
                *(uint32_t*)(smem + kc * 16384 + r * 128 + ((c8s ^ (r & 7)) << 4) + 4 * j) =
                    *(uint32_t*)&p0;
                *(uint32_t*)(smem + kc * 16384 + r2 * 128 + ((c8s ^ (r2 & 7)) << 4) + 4 * j) =
                    *(uint32_t*)&p1;
            }
        }
        // next layer's first slot sync orders these STS before the LDSMs; after the
        // final layer an explicit sync below does it.
    }
    __syncthreads();

    // ---- fused head: re-read h8 frags (R6-style), logits + log_softmax ----
    uint32_t pa[32][2];
    #pragma unroll
    for (int s = 0; s < 16; s++) {
        int rr = warp * 16 + (lane & 15);
        int cc = (s & 3) * 2 + (lane >> 4);
        uint32_t f[4];
        ldm_x4(f, sb + (s >> 2) * 16384 + rr * 128 + ((cc ^ (rr & 7)) << 4));
        pa[2 * s][0] = f[0]; pa[2 * s][1] = f[1];
        pa[2 * s + 1][0] = f[2]; pa[2 * s + 1][1] = f[3];
    }
    float a3[2][3] = {{0.f, 0.f, 0.f}, {0.f, 0.f, 0.f}};
    #pragma unroll
    for (int t = 0; t < 32; t++) {
        float2 x = __bfloat1622float2(*(__nv_bfloat162*)&pa[t][0]);
        float2 y = __bfloat1622float2(*(__nv_bfloat162*)&pa[t][1]);
        const int c0 = 8 * t + 2 * j;
        float w00 = sWl[c0 * 3 + 0], w01 = sWl[c0 * 3 + 1], w02 = sWl[c0 * 3 + 2];
        float w10 = sWl[c0 * 3 + 3], w11 = sWl[c0 * 3 + 4], w12 = sWl[c0 * 3 + 5];
        a3[0][0] += x.x * w00 + x.y * w10;
        a3[0][1] += x.x * w01 + x.y * w11;
        a3[0][2] += x.x * w02 + x.y * w12;
        a3[1][0] += y.x * w00 + y.y * w10;
        a3[1][1] += y.x * w01 + y.y * w11;
        a3[1][2] += y.x * w02 + y.y * w12;
    }
    #pragma unroll
    for (int off = 1; off <= 2; off <<= 1) {
        #pragma unroll
        for (int r = 0; r < 2; r++)
            #pragma unroll
            for (int c = 0; c < 3; c++)
                a3[r][c] += __shfl_xor_sync(0xffffffffu, a3[r][c], off);
    }
    if (j == 0) {
        const float bb0 = sbl[0], bb1 = sbl[1], bb2 = sbl[2];
        #pragma unroll
        for (int r = 0; r < 2; r++) {
            size_t e = m0 + warp * 16 + g + 8 * r;
            float l0 = a3[r][0] + bb0, l1 = a3[r][1] + bb1, l2 = a3[r][2] + bb2;
            float m = fmaxf(l0, fmaxf(l1, l2));
            float ls = m + logf(expf(l0 - m) + expf(l1 - m) + expf(l2 - m));
            out[e * 3 + 0] = l0 - ls;
            out[e * 3 + 1] = l1 - ls;
            out[e * 3 + 2] = l2 - ls;
        }
    }
}

// ============================ host ============================
extern "C" void kernel_launch(void* const* d_in, const int* in_sizes, int n_in,
                              void* d_out, int out_size) {
    const float* x  = (const float*)d_in[0];
    const int*   ei = (const int*)d_in[1];
    const float* ea = (const float*)d_in[2];
    const float* Wx = (const float*)d_in[3];
    const float* bx = (const float*)d_in[4];
    const float* W0 = (const float*)d_in[5];
    const float* b0 = (const float*)d_in[6];
    const float* Wm = (const float*)d_in[7];
    const float* bm = (const float*)d_in[8];
    const float* Wl = (const float*)d_in[9];
    const float* bl = (const float*)d_in[10];
    float* out = (float*)d_out;

    void* p;
    cudaGetSymbolAddress(&p, g_xb);    __nv_bfloat16* xb    = (__nv_bfloat16*)p;
    cudaGetSymbolAddress(&p, g_hnode); __nv_bfloat16* hnode = (__nv_bfloat16*)p;
    cudaGetSymbolAddress(&p, g_grow);  __nv_bfloat16* grow  = (__nv_bfloat16*)p;
    cudaGetSymbolAddress(&p, g_gcol);  __nv_bfloat16* gcol  = (__nv_bfloat16*)p;
    cudaGetSymbolAddress(&p, g_h0);    __nv_bfloat16* h0p   = (__nv_bfloat16*)p;
    cudaGetSymbolAddress(&p, g_Bx);    __nv_bfloat16* Bx    = (__nv_bfloat16*)p;
    cudaGetSymbolAddress(&p, g_B0a);   __nv_bfloat16* B0a   = (__nv_bfloat16*)p;
    cudaGetSymbolAddress(&p, g_B0b);   __nv_bfloat16* B0b   = (__nv_bfloat16*)p;
    cudaGetSymbolAddress(&p, g_Bm);    __nv_bfloat16* Bm    = (__nv_bfloat16*)p;

    constexpr int SMEM = 65536;
    constexpr int FSMEM = 65536 + 131072 + 8192 + 3072 + 16;   // 207,904
    cudaFuncSetAttribute(gemm_mma<256, 128, true,  true,  false>, cudaFuncAttributeMaxDynamicSharedMemorySize, SMEM);
    cudaFuncSetAttribute(gemm_mma<128, 256, false, false, true >, cudaFuncAttributeMaxDynamicSharedMemorySize, SMEM);
    cudaFuncSetAttribute(fused_mid, cudaFuncAttributeMaxDynamicSharedMemorySize, FSMEM);

    // --- prep ---
    detect_idx64<<<1, 32>>>((const unsigned*)ei);
    conv_f32_bf16<<<4096, 256>>>(x, xb, NNODES * 256);
    prep_Bt<<<dim3(4, 8, 1), dim3(32, 8)>>>(Wx, 0, 128, 256, 256, 0, 0, Bx);
    prep_Bt<<<dim3(8, 4, 1), dim3(32, 8)>>>(W0, 0,   256, 128, 128, 0, 0, B0a);
    prep_Bt<<<dim3(8, 4, 1), dim3(32, 8)>>>(W0, 128, 256, 128, 128, 0, 0, B0b);
    prep_Bt<<<dim3(8, 8, 8), dim3(32, 8)>>>(Wm, 0, 256, 256, 256, 65536, 65536, Bm);

    // --- node MLP: h_node = leaky(x @ Wx + bx) ---
    gemm_mma<256, 128, true, true, false><<<dim3(NNODES / 128, 1, 1), 256, SMEM>>>(
        xb, Bx, nullptr, bx, hnode, nullptr);
    // --- node-level edge-GEMM precompute: grow/gcol in one dual launch ---
    gemm_mma<128, 256, false, false, true><<<dim3(NNODES / 128, 2, 2), 256, SMEM>>>(
        hnode, B0a, B0b, nullptr, grow, gcol);
    // --- gather + ea matvec + combine + leaky -> h0 ---
    gather_combine_ea<<<NEDGES / 64, 256>>>(ei, ea, W0, b0, grow, gcol, h0p);
    // --- fused: 8 hidden layers + head + log_softmax ---
    fused_mid<<<NEDGES / 128, 256, FSMEM>>>(h0p, Bm, bm, Wl, bl, out);
}

// round 10
// speedup vs baseline: 2.6196x; 1.0211x over previous
#include <cuda_runtime.h>
#include <cuda_bf16.h>
#include <cstdint>

#define NNODES 65536
#define NEDGES 262144

// ============================ device scratch ============================
__device__ __align__(256) __nv_bfloat16 g_xb   [NNODES * 256];
__device__ __align__(256) __nv_bfloat16 g_hnode[NNODES * 128];
__device__ __align__(256) __nv_bfloat16 g_grow [NNODES * 256];
__device__ __align__(256) __nv_bfloat16 g_gcol [NNODES * 256];
__device__ __align__(256) __nv_bfloat16 g_h0   [(size_t)NEDGES * 256];
__device__ __align__(256) __nv_bfloat16 g_Bx [128 * 256];
__device__ __align__(256) __nv_bfloat16 g_B0a[256 * 128];
__device__ __align__(256) __nv_bfloat16 g_B0b[256 * 128];
__device__ __align__(256) __nv_bfloat16 g_Bm [8][256 * 256];
__device__ int g_idx64;

// ============================ PTX helpers (base PTX only) ============================
__device__ __forceinline__ uint32_t smem_u32(const void* p) {
    uint32_t a;
    asm("{ .reg .u64 t; cvta.to.shared.u64 t, %1; cvt.u32.u64 %0, t; }" : "=r"(a) : "l"(p));
    return a;
}
__device__ __forceinline__ void cp16(uint32_t dst, const void* src) {
    asm volatile("cp.async.cg.shared.global [%0], [%1], 16;" :: "r"(dst), "l"(src));
}
__device__ __forceinline__ void cp_commit() {
    asm volatile("cp.async.commit_group;" ::: "memory");
}
template <int N>
__device__ __forceinline__ void cp_wait() {
    asm volatile("cp.async.wait_group %0;" :: "n"(N) : "memory");
}
__device__ __forceinline__ void ldm_x4(uint32_t* r, uint32_t addr) {
    asm volatile("ldmatrix.sync.aligned.m8n8.x4.shared.b16 {%0,%1,%2,%3}, [%4];"
                 : "=r"(r[0]), "=r"(r[1]), "=r"(r[2]), "=r"(r[3]) : "r"(addr));
}
__device__ __forceinline__ void ldm_x2(uint32_t* r, uint32_t addr) {
    asm volatile("ldmatrix.sync.aligned.m8n8.x2.shared.b16 {%0,%1}, [%2];"
                 : "=r"(r[0]), "=r"(r[1]) : "r"(addr));
}
__device__ __forceinline__ void mma_bf16(float* c, const uint32_t* a, const uint32_t* b) {
    asm volatile(
        "mma.sync.aligned.m16n8k16.row.col.f32.bf16.bf16.f32 "
        "{%0,%1,%2,%3}, {%4,%5,%6,%7}, {%8,%9}, {%0,%1,%2,%3};"
        : "+f"(c[0]), "+f"(c[1]), "+f"(c[2]), "+f"(c[3])
        : "r"(a[0]), "r"(a[1]), "r"(a[2]), "r"(a[3]), "r"(b[0]), "r"(b[1]));
}

// ============================ prep 1: idx detect + x conversion ============================
__global__ void prep_misc(const float* __restrict__ x, const unsigned* __restrict__ ei) {
    if (blockIdx.x == 0 && threadIdx.x == 0) {
        int is64 = 1;
        for (int i = 0; i < 512; i++)
            if (ei[2 * i + 1] != 0u) { is64 = 0; break; }
        g_idx64 = is64;
    }
    for (int i = blockIdx.x * blockDim.x + threadIdx.x; i < NNODES * 256;
         i += gridDim.x * blockDim.x)
        g_xb[i] = __float2bfloat16(x[i]);
}

// ============================ prep 2: all weight transposes in one launch ============================
// 608 blocks: [0,32) Bx 4x8 tiles; [32,64) B0a 8x4; [64,96) B0b 8x4; [96,608) Bm 8 layers x 8x8.
__global__ void prep_W(const float* __restrict__ Wx, const float* __restrict__ W0,
                       const float* __restrict__ Wm) {
    __shared__ float tile[32][33];
    const int bid = blockIdx.x;
    const float* W; __nv_bfloat16* B;
    int row0, ldW, Ksrc, Kpad, tn, tk;
    if (bid < 32)       { W = Wx; B = g_Bx;  row0 = 0;   ldW = 128; Ksrc = 256; Kpad = 256; tn = bid >> 3;         tk = bid & 7; }
    else if (bid < 64)  { W = W0; B = g_B0a; row0 = 0;   ldW = 256; Ksrc = 128; Kpad = 128; tn = (bid - 32) >> 2;  tk = (bid - 32) & 3; }
    else if (bid < 96)  { W = W0; B = g_B0b; row0 = 128; ldW = 256; Ksrc = 128; Kpad = 128; tn = (bid - 64) >> 2;  tk = (bid - 64) & 3; }
    else {
        int b = bid - 96, L = b >> 6, t = b & 63;
        W = Wm + (size_t)L * 65536; B = &g_Bm[L][0];
        row0 = 0; ldW = 256; Ksrc = 256; Kpad = 256; tn = t >> 3; tk = t & 7;
    }
    const int n0 = tn * 32, k0 = tk * 32;
    const int tx = threadIdx.x, ty = threadIdx.y;
    #pragma unroll
    for (int r = 0; r < 32; r += 8) {
        int k = k0 + ty + r;
        tile[ty + r][tx] = (k < Ksrc) ? W[(size_t)(row0 + k) * ldW + n0 + tx] : 0.f;
    }
    __syncthreads();
    #pragma unroll
    for (int r = 0; r < 32; r += 8) {
        int n = n0 + ty + r;
        B[(size_t)n * Kpad + k0 + tx] = __float2bfloat16(tile[tx][ty + r]);
    }
}

// ============================ generic bf16 HMMA GEMM (prep stages) ============================
template <int K, int NOUT, bool LEAKY, bool HASBIAS, bool DUAL>
__global__ void __launch_bounds__(256)
gemm_mma(const __nv_bfloat16* __restrict__ A, const __nv_bfloat16* __restrict__ Bin,
         const __nv_bfloat16* __restrict__ B2, const float* __restrict__ bias,
         __nv_bfloat16* __restrict__ Out1, __nv_bfloat16* __restrict__ Out2) {
    static_assert(K % 64 == 0, "");
    constexpr int KT = K / 64;
    extern __shared__ char smem[];
    const uint32_t sb = smem_u32(smem);
    constexpr uint32_t STAGE = 32768, BOFF = 16384;

    const __nv_bfloat16* B = (DUAL && blockIdx.z) ? B2 : Bin;
    __nv_bfloat16* Out = (DUAL && blockIdx.z) ? Out2 : Out1;

    const int tid = threadIdx.x;
    const int lane = tid & 31, warp = tid >> 5;
    const int warp_m = warp & 1;
    const int warp_n = warp >> 1;
    const size_t m0 = (size_t)blockIdx.x * 128;
    const int n0 = blockIdx.y * 128;

    float acc[4][4][4];
    #pragma unroll
    for (int i = 0; i < 4; i++)
        #pragma unroll
        for (int j = 0; j < 4; j++)
            #pragma unroll
            for (int q = 0; q < 4; q++) acc[i][j][q] = 0.f;

    auto load_stage = [&](int stage, int kt) {
        const uint32_t base = sb + stage * STAGE;
        #pragma unroll
        for (int i = 0; i < 4; i++) {
            int idx = tid + i * 256;
            int r = idx >> 3, c8 = idx & 7;
            uint32_t dst = base + r * 128 + (((c8 ^ (r & 7))) << 4);
            cp16(dst, A + (m0 + r) * K + kt * 64 + c8 * 8);
        }
        #pragma unroll
        for (int i = 0; i < 4; i++) {
            int idx = tid + i * 256;
            int r = idx >> 3, c8 = idx & 7;
            uint32_t dst = base + BOFF + r * 128 + (((c8 ^ (r & 7))) << 4);
            cp16(dst, B + (size_t)(n0 + r) * K + kt * 64 + c8 * 8);
        }
    };

    load_stage(0, 0);
    cp_commit();

    for (int kt = 0; kt < KT; kt++) {
        if (kt + 1 < KT) { load_stage((kt + 1) & 1, kt + 1); cp_commit(); cp_wait<1>(); }
        else             { cp_wait<0>(); }
        __syncthreads();

        const uint32_t abase = sb + (kt & 1) * STAGE;
        const uint32_t bbase = abase + BOFF;
        #pragma unroll
        for (int ks = 0; ks < 4; ks++) {
            uint32_t af[4][4];
            #pragma unroll
            for (int mi = 0; mi < 4; mi++) {
                int r = warp_m * 64 + mi * 16 + (lane & 15);
                int c8 = ks * 2 + (lane >> 4);
                ldm_x4(af[mi], abase + r * 128 + ((c8 ^ (r & 7)) << 4));
            }
            uint32_t bf2[4][2];
            #pragma unroll
            for (int ni = 0; ni < 4; ni++) {
                int r = warp_n * 32 + ni * 8 + (lane & 7);
                int c8 = ks * 2 + ((lane >> 3) & 1);
                ldm_x2(bf2[ni], bbase + r * 128 + ((c8 ^ (r & 7)) << 4));
            }
            #pragma unroll
            for (int mi = 0; mi < 4; mi++)
                #pragma unroll
                for (int ni = 0; ni < 4; ni++)
                    mma_bf16(acc[mi][ni], af[mi], bf2[ni]);
        }
        __syncthreads();
    }

    const int g = lane >> 2;
    #pragma unroll
    for (int ni = 0; ni < 4; ni++) {
        const int col = n0 + warp_n * 32 + ni * 8 + ((lane & 3) << 1);
        float bb0 = 0.f, bb1 = 0.f;
        if (HASBIAS) { bb0 = __ldg(bias + col); bb1 = __ldg(bias + col + 1); }
        #pragma unroll
        for (int mi = 0; mi < 4; mi++) {
            const size_t r0 = m0 + warp_m * 64 + mi * 16 + g;
            float v0 = acc[mi][ni][0] + bb0, v1 = acc[mi][ni][1] + bb1;
            float v2 = acc[mi][ni][2] + bb0, v3 = acc[mi][ni][3] + bb1;
            if (LEAKY) {
                v0 = v0 >= 0.f ? v0 : 0.01f * v0;  v1 = v1 >= 0.f ? v1 : 0.01f * v1;
                v2 = v2 >= 0.f ? v2 : 0.01f * v2;  v3 = v3 >= 0.f ? v3 : 0.01f * v3;
            }
            __nv_bfloat162 p0 = __floats2bfloat162_rn(v0, v1);
            __nv_bfloat162 p1 = __floats2bfloat162_rn(v2, v3);
            *(uint32_t*)(Out + r0 * NOUT + col)       = *(uint32_t*)&p0;
            *(uint32_t*)(Out + (r0 + 8) * NOUT + col) = *(uint32_t*)&p1;
        }
    }
}

// ============================ gather + ea-matvec + combine ============================
__global__ void __launch_bounds__(256)
gather_combine_ea(const int* __restrict__ ei, const float* __restrict__ ea,
                  const float* __restrict__ W0, const float* __restrict__ b0,
                  const __nv_bfloat16* __restrict__ gr, const __nv_bfloat16* __restrict__ gc,
                  __nv_bfloat16* __restrict__ h0) {
    __shared__ float sea[64][16];
    __shared__ int srow[64], scol[64];
    const int t = threadIdx.x;
    const long e0 = (long)blockIdx.x * 64;
    const int is64 = g_idx64;
    if (t < 64) {
        long e = e0 + t;
        if (is64) { srow[t] = ei[2 * e]; scol[t] = ei[2 * (NEDGES + e)]; }
        else      { srow[t] = ei[e];     scol[t] = ei[NEDGES + e]; }
    }
    {
        int e = t >> 2, k = (t & 3) * 4;
        *(float4*)&sea[e][k] = *(const float4*)(ea + (e0 + e) * 16 + k);
    }
    const int cp = t & 127;
    float2 w[16];
    #pragma unroll
    for (int k = 0; k < 16; k++)
        w[k] = *(const float2*)(W0 + (size_t)(256 + k) * 256 + 2 * cp);
    const float2 bb = *(const float2*)(b0 + 2 * cp);
    __syncthreads();

    const int eo = t >> 7;
    for (int i = eo; i < 64; i += 2) {
        float v0 = bb.x, v1 = bb.y;
        #pragma unroll
        for (int k = 0; k < 16; k++) {
            float s = sea[i][k];
            v0 += s * w[k].x;
            v1 += s * w[k].y;
        }
        const __nv_bfloat162 gv = ((const __nv_bfloat162*)(gr + (size_t)srow[i] * 256))[cp];
        const __nv_bfloat162 cv = ((const __nv_bfloat162*)(gc + (size_t)scol[i] * 256))[cp];
        float2 gb = __bfloat1622float2(gv);
        float2 cb = __bfloat1622float2(cv);
        v0 += gb.x + cb.x;
        v1 += gb.y + cb.y;
        v0 = v0 >= 0.f ? v0 : 0.01f * v0;
        v1 = v1 >= 0.f ? v1 : 0.01f * v1;
        ((__nv_bfloat162*)(h0 + (size_t)(e0 + i) * 256))[cp] = __floats2bfloat162_rn(v0, v1);
    }
}

// ============================ fused 8 mid layers + head (16 warps, SMEM activations) ============================
// CTA = 128 edges, 512 threads, warp grid 4(M)x4(N): warp = 32 edges x 64 cols.
// Activations in SMEM A region [0,64K); weight ring 4x32KB K-quarter slots, prefetch depth 3.
__global__ void __launch_bounds__(512, 1)
fused_mid(const __nv_bfloat16* __restrict__ h0, const __nv_bfloat16* __restrict__ Bm,
          const float* __restrict__ bm, const float* __restrict__ Wl,
          const float* __restrict__ bl, float* __restrict__ out) {
    extern __shared__ char smem[];
    const uint32_t sb = smem_u32(smem);
    constexpr uint32_t RINGOFF = 65536;               // ring: 4 x 32KB at [64K, 192K)
    constexpr uint32_t PARAM = 65536 + 131072;
    float* sbias = (float*)(smem + PARAM);            // 8 x 256 fp32
    float* sWl   = (float*)(smem + PARAM + 8192);     // 256 x 3 fp32
    float* sbl   = (float*)(smem + PARAM + 8192 + 3072);

    const int tid = threadIdx.x, lane = tid & 31, warp = tid >> 5;
    const int warp_m = warp >> 2;                     // 0..3 -> M offset *32
    const int warp_n = warp & 3;                      // 0..3 -> N offset *64
    const size_t m0 = (size_t)blockIdx.x * 128;

    for (int i = tid; i < 2048; i += 512) sbias[i] = bm[i];
    for (int i = tid; i < 768; i += 512) sWl[i] = Wl[i];
    if (tid < 3) sbl[tid] = bl[tid];

    // B ring loader: slot s -> layer s>>2, K-quarter s&3, region s&3
    auto loadB = [&](int s) {
        const uint32_t base = sb + RINGOFF + (uint32_t)(s & 3) * 32768u;
        const __nv_bfloat16* src = Bm + (size_t)(s >> 2) * 65536 + (s & 3) * 64;
        #pragma unroll
        for (int i = 0; i < 4; i++) {
            int idx = tid + i * 512;
            int r = idx >> 3, c8 = idx & 7;
            cp16(base + r * 128 + ((c8 ^ (r & 7)) << 4), src + (size_t)r * 256 + c8 * 8);
        }
    };

    // A tile (h0, 128x256) -> A region as 4 chunks of [128][64], XOR swizzle  (group G0)
    #pragma unroll
    for (int kc = 0; kc < 4; kc++)
        #pragma unroll
        for (int i = 0; i < 2; i++) {
            int idx = tid + i * 512;
            int r = idx >> 3, c8 = idx & 7;
            cp16(sb + kc * 16384 + r * 128 + ((c8 ^ (r & 7)) << 4),
                 h0 + (m0 + r) * 256 + kc * 64 + c8 * 8);
        }
    cp_commit();                 // G0 = A
    loadB(0); cp_commit();       // G1
    loadB(1); cp_commit();       // G2
    loadB(2); cp_commit();       // G3
    __syncthreads();             // params visible

    const int g = lane >> 2, j = lane & 3;
    const int rr_lo = ((lane >> 4) << 3) + (lane & 7);
    const int ar_lo = warp_m * 32 + (lane & 15);

    for (int l = 0; l < 8; ++l) {
        float acc[2][8][4];
        #pragma unroll
        for (int nt = 0; nt < 8; nt++) {
            float2 bb = *(const float2*)(sbias + (l << 8) + warp_n * 64 + 8 * nt + 2 * j);
            #pragma unroll
            for (int mi = 0; mi < 2; mi++) {
                acc[mi][nt][0] = bb.x; acc[mi][nt][1] = bb.y;
                acc[mi][nt][2] = bb.x; acc[mi][nt][3] = bb.y;
            }
        }
        #pragma unroll
        for (int kh = 0; kh < 4; kh++) {
            const int s = l * 4 + kh;
            cp_wait<2>();
            __syncthreads();
            if (s + 3 < 32) loadB(s + 3);
            cp_commit();
            const uint32_t bbase = sb + RINGOFF + (uint32_t)(s & 3) * 32768u;
            const uint32_t achk = sb + kh * 16384;
            #pragma unroll
            for (int ksl = 0; ksl < 4; ksl++) {
                const int cca = ksl * 2 + (lane >> 4);
                uint32_t a0[4], a1[4];
                int r0 = ar_lo;
                ldm_x4(a0, achk + r0 * 128 + ((cca ^ (r0 & 7)) << 4));
                int r1 = ar_lo + 16;
                ldm_x4(a1, achk + r1 * 128 + ((cca ^ (r1 & 7)) << 4));
                const int ccb = ksl * 2 + ((lane >> 3) & 1);
                #pragma unroll
                for (int bt = 0; bt < 4; bt++) {
                    int rr = warp_n * 64 + bt * 16 + rr_lo;
                    uint32_t bf[4];
                    ldm_x4(bf, bbase + rr * 128 + ((ccb ^ (rr & 7)) << 4));
                    mma_bf16(acc[0][2 * bt],     a0, bf);
                    mma_bf16(acc[0][2 * bt + 1], a0, bf + 2);
                    mma_bf16(acc[1][2 * bt],     a1, bf);
                    mma_bf16(acc[1][2 * bt + 1], a1, bf + 2);
                }
            }
        }
        __syncthreads();   // all A reads of this layer complete before overwrite
        // epilogue: leaky + bf16 + STS back into A region
        #pragma unroll
        for (int mi = 0; mi < 2; mi++) {
            const int r  = warp_m * 32 + mi * 16 + g;
            const int r2 = r + 8;
            #pragma unroll
            for (int nt = 0; nt < 8; nt++) {
                float v0 = acc[mi][nt][0], v1 = acc[mi][nt][1];
                float v2 = acc[mi][nt][2], v3 = acc[mi][nt][3];
                v0 = v0 >= 0.f ? v0 : 0.01f * v0;  v1 = v1 >= 0.f ? v1 : 0.01f * v1;
                v2 = v2 >= 0.f ? v2 : 0.01f * v2;  v3 = v3 >= 0.f ? v3 : 0.01f * v3;
                __nv_bfloat162 p0 = __floats2bfloat162_rn(v0, v1);
                __nv_bfloat162 p1 = __floats2bfloat162_rn(v2, v3);
                const int c = warp_n * 64 + nt * 8;
                const int kc = c >> 6, c8s = (c >> 3) & 7;
                *(uint32_t*)(smem + kc * 16384 + r * 128 + ((c8s ^ (r & 7)) << 4) + 4 * j) =
                    *(uint32_t*)&p0;
                *(uint32_t*)(smem + kc * 16384 + r2 * 128 + ((c8s ^ (r2 & 7)) << 4) + 4 * j) =
                    *(uint32_t*)&p1;
            }
        }
        // next layer's first phase sync orders these STS before the LDSMs.
    }
    __syncthreads();

    // ---- fused head (warps 0-7): logits + log_softmax ----
    if (warp < 8) {
        uint32_t pa[32][2];
        #pragma unroll
        for (int s = 0; s < 16; s++) {
            int rr = warp * 16 + (lane & 15);
            int cc = (s & 3) * 2 + (lane >> 4);
            uint32_t f[4];
            ldm_x4(f, sb + (s >> 2) * 16384 + rr * 128 + ((cc ^ (rr & 7)) << 4));
            pa[2 * s][0] = f[0]; pa[2 * s][1] = f[1];
            pa[2 * s + 1][0] = f[2]; pa[2 * s + 1][1] = f[3];
        }
        float a3[2][3] = {{0.f, 0.f, 0.f}, {0.f, 0.f, 0.f}};
        #pragma unroll
        for (int t = 0; t < 32; t++) {
            float2 x = __bfloat1622float2(*(__nv_bfloat162*)&pa[t][0]);
            float2 y = __bfloat1622float2(*(__nv_bfloat162*)&pa[t][1]);
            const int c0 = 8 * t + 2 * j;
            float w00 = sWl[c0 * 3 + 0], w01 = sWl[c0 * 3 + 1], w02 = sWl[c0 * 3 + 2];
            float w10 = sWl[c0 * 3 + 3], w11 = sWl[c0 * 3 + 4], w12 = sWl[c0 * 3 + 5];
            a3[0][0] += x.x * w00 + x.y * w10;
            a3[0][1] += x.x * w01 + x.y * w11;
            a3[0][2] += x.x * w02 + x.y * w12;
            a3[1][0] += y.x * w00 + y.y * w10;
            a3[1][1] += y.x * w01 + y.y * w11;
            a3[1][2] += y.x * w02 + y.y * w12;
        }
        #pragma unroll
        for (int off = 1; off <= 2; off <<= 1) {
            #pragma unroll
            for (int r = 0; r < 2; r++)
                #pragma unroll
                for (int c = 0; c < 3; c++)
                    a3[r][c] += __shfl_xor_sync(0xffffffffu, a3[r][c], off);
        }
        if (j == 0) {
            const float bb0 = sbl[0], bb1 = sbl[1], bb2 = sbl[2];
            #pragma unroll
            for (int r = 0; r < 2; r++) {
                size_t e = m0 + warp * 16 + g + 8 * r;
                float l0 = a3[r][0] + bb0, l1 = a3[r][1] + bb1, l2 = a3[r][2] + bb2;
                float m = fmaxf(l0, fmaxf(l1, l2));
                float ls = m + logf(expf(l0 - m) + expf(l1 - m) + expf(l2 - m));
                out[e * 3 + 0] = l0 - ls;
                out[e * 3 + 1] = l1 - ls;
                out[e * 3 + 2] = l2 - ls;
            }
        }
    }
}

// ============================ host ============================
extern "C" void kernel_launch(void* const* d_in, const int* in_sizes, int n_in,
                              void* d_out, int out_size) {
    const float* x  = (const float*)d_in[0];
    const int*   ei = (const int*)d_in[1];
    const float* ea = (const float*)d_in[2];
    const float* Wx = (const float*)d_in[3];
    const float* bx = (const float*)d_in[4];
    const float* W0 = (const float*)d_in[5];
    const float* b0 = (const float*)d_in[6];
    const float* Wm = (const float*)d_in[7];
    const float* bm = (const float*)d_in[8];
    const float* Wl = (const float*)d_in[9];
    const float* bl = (const float*)d_in[10];
    float* out = (float*)d_out;

    void* p;
    cudaGetSymbolAddress(&p, g_xb);    __nv_bfloat16* xb    = (__nv_bfloat16*)p;
    cudaGetSymbolAddress(&p, g_hnode); __nv_bfloat16* hnode = (__nv_bfloat16*)p;
    cudaGetSymbolAddress(&p, g_grow);  __nv_bfloat16* grow  = (__nv_bfloat16*)p;
    cudaGetSymbolAddress(&p, g_gcol);  __nv_bfloat16* gcol  = (__nv_bfloat16*)p;
    cudaGetSymbolAddress(&p, g_h0);    __nv_bfloat16* h0p   = (__nv_bfloat16*)p;
    cudaGetSymbolAddress(&p, g_Bx);    __nv_bfloat16* Bx    = (__nv_bfloat16*)p;
    cudaGetSymbolAddress(&p, g_B0a);   __nv_bfloat16* B0a   = (__nv_bfloat16*)p;
    cudaGetSymbolAddress(&p, g_B0b);   __nv_bfloat16* B0b   = (__nv_bfloat16*)p;
    cudaGetSymbolAddress(&p, g_Bm);    __nv_bfloat16* Bm    = (__nv_bfloat16*)p;

    constexpr int SMEM = 65536;
    constexpr int FSMEM = 65536 + 131072 + 8192 + 3072 + 16;   // 207,904
    cudaFuncSetAttribute(gemm_mma<256, 128, true,  true,  false>, cudaFuncAttributeMaxDynamicSharedMemorySize, SMEM);
    cudaFuncSetAttribute(gemm_mma<128, 256, false, false, true >, cudaFuncAttributeMaxDynamicSharedMemorySize, SMEM);
    cudaFuncSetAttribute(fused_mid, cudaFuncAttributeMaxDynamicSharedMemorySize, FSMEM);

    // 1: idx detect + x -> bf16
    prep_misc<<<4096, 256>>>(x, (const unsigned*)ei);
    // 2: all weight transposes
    prep_W<<<608, dim3(32, 8)>>>(Wx, W0, Wm);
    // 3: node MLP: h_node = leaky(x @ Wx + bx)
    gemm_mma<256, 128, true, true, false><<<dim3(NNODES / 128, 1, 1), 256, SMEM>>>(
        xb, Bx, nullptr, bx, hnode, nullptr);
    // 4: node-level edge-GEMM precompute: grow/gcol in one dual launch
    gemm_mma<128, 256, false, false, true><<<dim3(NNODES / 128, 2, 2), 256, SMEM>>>(
        hnode, B0a, B0b, nullptr, grow, gcol);
    // 5: gather + ea matvec + combine + leaky -> h0
    gather_combine_ea<<<NEDGES / 64, 256>>>(ei, ea, W0, b0, grow, gcol, h0p);
    // 6: fused: 8 hidden layers + head + log_softmax   (<- ncu capture target)
    fused_mid<<<NEDGES / 128, 512, FSMEM>>>(h0p, Bm, bm, Wl, bl, out);
}

// round 11
// speedup vs baseline: 2.6941x; 1.0284x over previous
#include <cuda_runtime.h>
#include <cuda_bf16.h>
#include <cstdint>

#define NNODES 65536
#define NEDGES 262144

// ============================ device scratch ============================
__device__ __align__(256) __nv_bfloat16 g_xb   [NNODES * 256];
__device__ __align__(256) __nv_bfloat16 g_hnode[NNODES * 128];
__device__ __align__(256) __nv_bfloat16 g_grow [NNODES * 256];
__device__ __align__(256) __nv_bfloat16 g_gcol [NNODES * 256];
__device__ __align__(256) __nv_bfloat16 g_h0   [(size_t)NEDGES * 256];
__device__ __align__(256) __nv_bfloat16 g_Bx [128 * 256];
__device__ __align__(256) __nv_bfloat16 g_B0a[256 * 128];
__device__ __align__(256) __nv_bfloat16 g_B0b[256 * 128];
__device__ __align__(256) __nv_bfloat16 g_Bm [8][256 * 256];
__device__ int g_idx64;

// ============================ PTX helpers (base PTX only) ============================
__device__ __forceinline__ uint32_t smem_u32(const void* p) {
    uint32_t a;
    asm("{ .reg .u64 t; cvta.to.shared.u64 t, %1; cvt.u32.u64 %0, t; }" : "=r"(a) : "l"(p));
    return a;
}
__device__ __forceinline__ void cp16(uint32_t dst, const void* src) {
    asm volatile("cp.async.cg.shared.global [%0], [%1], 16;" :: "r"(dst), "l"(src));
}
__device__ __forceinline__ void cp_commit() {
    asm volatile("cp.async.commit_group;" ::: "memory");
}
template <int N>
__device__ __forceinline__ void cp_wait() {
    asm volatile("cp.async.wait_group %0;" :: "n"(N) : "memory");
}
__device__ __forceinline__ void ldm_x4(uint32_t* r, uint32_t addr) {
    asm volatile("ldmatrix.sync.aligned.m8n8.x4.shared.b16 {%0,%1,%2,%3}, [%4];"
                 : "=r"(r[0]), "=r"(r[1]), "=r"(r[2]), "=r"(r[3]) : "r"(addr));
}
__device__ __forceinline__ void ldm_x2(uint32_t* r, uint32_t addr) {
    asm volatile("ldmatrix.sync.aligned.m8n8.x2.shared.b16 {%0,%1}, [%2];"
                 : "=r"(r[0]), "=r"(r[1]) : "r"(addr));
}
__device__ __forceinline__ void mma_bf16(float* c, const uint32_t* a, const uint32_t* b) {
    asm volatile(
        "mma.sync.aligned.m16n8k16.row.col.f32.bf16.bf16.f32 "
        "{%0,%1,%2,%3}, {%4,%5,%6,%7}, {%8,%9}, {%0,%1,%2,%3};"
        : "+f"(c[0]), "+f"(c[1]), "+f"(c[2]), "+f"(c[3])
        : "r"(a[0]), "r"(a[1]), "r"(a[2]), "r"(a[3]), "r"(b[0]), "r"(b[1]));
}

// ============================ prep 1: idx detect + x conversion ============================
__global__ void prep_misc(const float* __restrict__ x, const unsigned* __restrict__ ei) {
    if (blockIdx.x == 0 && threadIdx.x == 0) {
        int is64 = 1;
        for (int i = 0; i < 512; i++)
            if (ei[2 * i + 1] != 0u) { is64 = 0; break; }
        g_idx64 = is64;
    }
    for (int i = blockIdx.x * blockDim.x + threadIdx.x; i < NNODES * 256;
         i += gridDim.x * blockDim.x)
        g_xb[i] = __float2bfloat16(x[i]);
}

// ============================ prep 2: all weight transposes in one launch ============================
__global__ void prep_W(const float* __restrict__ Wx, const float* __restrict__ W0,
                       const float* __restrict__ Wm) {
    __shared__ float tile[32][33];
    const int bid = blockIdx.x;
    const float* W; __nv_bfloat16* B;
    int row0, ldW, Ksrc, Kpad, tn, tk;
    if (bid < 32)       { W = Wx; B = g_Bx;  row0 = 0;   ldW = 128; Ksrc = 256; Kpad = 256; tn = bid >> 3;         tk = bid & 7; }
    else if (bid < 64)  { W = W0; B = g_B0a; row0 = 0;   ldW = 256; Ksrc = 128; Kpad = 128; tn = (bid - 32) >> 2;  tk = (bid - 32) & 3; }
    else if (bid < 96)  { W = W0; B = g_B0b; row0 = 128; ldW = 256; Ksrc = 128; Kpad = 128; tn = (bid - 64) >> 2;  tk = (bid - 64) & 3; }
    else {
        int b = bid - 96, L = b >> 6, t = b & 63;
        W = Wm + (size_t)L * 65536; B = &g_Bm[L][0];
        row0 = 0; ldW = 256; Ksrc = 256; Kpad = 256; tn = t >> 3; tk = t & 7;
    }
    const int n0 = tn * 32, k0 = tk * 32;
    const int tx = threadIdx.x, ty = threadIdx.y;
    #pragma unroll
    for (int r = 0; r < 32; r += 8) {
        int k = k0 + ty + r;
        tile[ty + r][tx] = (k < Ksrc) ? W[(size_t)(row0 + k) * ldW + n0 + tx] : 0.f;
    }
    __syncthreads();
    #pragma unroll
    for (int r = 0; r < 32; r += 8) {
        int n = n0 + ty + r;
        B[(size_t)n * Kpad + k0 + tx] = __float2bfloat16(tile[tx][ty + r]);
    }
}

// ============================ generic bf16 HMMA GEMM (prep stages) ============================
template <int K, int NOUT, bool LEAKY, bool HASBIAS, bool DUAL>
__global__ void __launch_bounds__(256)
gemm_mma(const __nv_bfloat16* __restrict__ A, const __nv_bfloat16* __restrict__ Bin,
         const __nv_bfloat16* __restrict__ B2, const float* __restrict__ bias,
         __nv_bfloat16* __restrict__ Out1, __nv_bfloat16* __restrict__ Out2) {
    static_assert(K % 64 == 0, "");
    constexpr int KT = K / 64;
    extern __shared__ char smem[];
    const uint32_t sb = smem_u32(smem);
    constexpr uint32_t STAGE = 32768, BOFF = 16384;

    const __nv_bfloat16* B = (DUAL && blockIdx.z) ? B2 : Bin;
    __nv_bfloat16* Out = (DUAL && blockIdx.z) ? Out2 : Out1;

    const int tid = threadIdx.x;
    const int lane = tid & 31, warp = tid >> 5;
    const int warp_m = warp & 1;
    const int warp_n = warp >> 1;
    const size_t m0 = (size_t)blockIdx.x * 128;
    const int n0 = blockIdx.y * 128;

    float acc[4][4][4];
    #pragma unroll
    for (int i = 0; i < 4; i++)
        #pragma unroll
        for (int j = 0; j < 4; j++)
            #pragma unroll
            for (int q = 0; q < 4; q++) acc[i][j][q] = 0.f;

    auto load_stage = [&](int stage, int kt) {
        const uint32_t base = sb + stage * STAGE;
        #pragma unroll
        for (int i = 0; i < 4; i++) {
            int idx = tid + i * 256;
            int r = idx >> 3, c8 = idx & 7;
            uint32_t dst = base + r * 128 + (((c8 ^ (r & 7))) << 4);
            cp16(dst, A + (m0 + r) * K + kt * 64 + c8 * 8);
        }
        #pragma unroll
        for (int i = 0; i < 4; i++) {
            int idx = tid + i * 256;
            int r = idx >> 3, c8 = idx & 7;
            uint32_t dst = base + BOFF + r * 128 + (((c8 ^ (r & 7))) << 4);
            cp16(dst, B + (size_t)(n0 + r) * K + kt * 64 + c8 * 8);
        }
    };

    load_stage(0, 0);
    cp_commit();

    for (int kt = 0; kt < KT; kt++) {
        if (kt + 1 < KT) { load_stage((kt + 1) & 1, kt + 1); cp_commit(); cp_wait<1>(); }
        else             { cp_wait<0>(); }
        __syncthreads();

        const uint32_t abase = sb + (kt & 1) * STAGE;
        const uint32_t bbase = abase + BOFF;
        #pragma unroll
        for (int ks = 0; ks < 4; ks++) {
            uint32_t af[4][4];
            #pragma unroll
            for (int mi = 0; mi < 4; mi++) {
                int r = warp_m * 64 + mi * 16 + (lane & 15);
                int c8 = ks * 2 + (lane >> 4);
                ldm_x4(af[mi], abase + r * 128 + ((c8 ^ (r & 7)) << 4));
            }
            uint32_t bf2[4][2];
            #pragma unroll
            for (int ni = 0; ni < 4; ni++) {
                int r = warp_n * 32 + ni * 8 + (lane & 7);
                int c8 = ks * 2 + ((lane >> 3) & 1);
                ldm_x2(bf2[ni], bbase + r * 128 + ((c8 ^ (r & 7)) << 4));
            }
            #pragma unroll
            for (int mi = 0; mi < 4; mi++)
                #pragma unroll
                for (int ni = 0; ni < 4; ni++)
                    mma_bf16(acc[mi][ni], af[mi], bf2[ni]);
        }
        __syncthreads();
    }

    const int g = lane >> 2;
    #pragma unroll
    for (int ni = 0; ni < 4; ni++) {
        const int col = n0 + warp_n * 32 + ni * 8 + ((lane & 3) << 1);
        float bb0 = 0.f, bb1 = 0.f;
        if (HASBIAS) { bb0 = __ldg(bias + col); bb1 = __ldg(bias + col + 1); }
        #pragma unroll
        for (int mi = 0; mi < 4; mi++) {
            const size_t r0 = m0 + warp_m * 64 + mi * 16 + g;
            float v0 = acc[mi][ni][0] + bb0, v1 = acc[mi][ni][1] + bb1;
            float v2 = acc[mi][ni][2] + bb0, v3 = acc[mi][ni][3] + bb1;
            if (LEAKY) {
                v0 = v0 >= 0.f ? v0 : 0.01f * v0;  v1 = v1 >= 0.f ? v1 : 0.01f * v1;
                v2 = v2 >= 0.f ? v2 : 0.01f * v2;  v3 = v3 >= 0.f ? v3 : 0.01f * v3;
            }
            __nv_bfloat162 p0 = __floats2bfloat162_rn(v0, v1);
            __nv_bfloat162 p1 = __floats2bfloat162_rn(v2, v3);
            *(uint32_t*)(Out + r0 * NOUT + col)       = *(uint32_t*)&p0;
            *(uint32_t*)(Out + (r0 + 8) * NOUT + col) = *(uint32_t*)&p1;
        }
    }
}

// ============================ gather + ea-matvec + combine ============================
__global__ void __launch_bounds__(256)
gather_combine_ea(const int* __restrict__ ei, const float* __restrict__ ea,
                  const float* __restrict__ W0, const float* __restrict__ b0,
                  const __nv_bfloat16* __restrict__ gr, const __nv_bfloat16* __restrict__ gc,
                  __nv_bfloat16* __restrict__ h0) {
    __shared__ float sea[64][16];
    __shared__ int srow[64], scol[64];
    const int t = threadIdx.x;
    const long e0 = (long)blockIdx.x * 64;
    const int is64 = g_idx64;
    if (t < 64) {
        long e = e0 + t;
        if (is64) { srow[t] = ei[2 * e]; scol[t] = ei[2 * (NEDGES + e)]; }
        else      { srow[t] = ei[e];     scol[t] = ei[NEDGES + e]; }
    }
    {
        int e = t >> 2, k = (t & 3) * 4;
        *(float4*)&sea[e][k] = *(const float4*)(ea + (e0 + e) * 16 + k);
    }
    const int cp = t & 127;
    float2 w[16];
    #pragma unroll
    for (int k = 0; k < 16; k++)
        w[k] = *(const float2*)(W0 + (size_t)(256 + k) * 256 + 2 * cp);
    const float2 bb = *(const float2*)(b0 + 2 * cp);
    __syncthreads();

    const int eo = t >> 7;
    for (int i = eo; i < 64; i += 2) {
        float v0 = bb.x, v1 = bb.y;
        #pragma unroll
        for (int k = 0; k < 16; k++) {
            float s = sea[i][k];
            v0 += s * w[k].x;
            v1 += s * w[k].y;
        }
        const __nv_bfloat162 gv = ((const __nv_bfloat162*)(gr + (size_t)srow[i] * 256))[cp];
        const __nv_bfloat162 cv = ((const __nv_bfloat162*)(gc + (size_t)scol[i] * 256))[cp];
        float2 gb = __bfloat1622float2(gv);
        float2 cb = __bfloat1622float2(cv);
        v0 += gb.x + cb.x;
        v1 += gb.y + cb.y;
        v0 = v0 >= 0.f ? v0 : 0.01f * v0;
        v1 = v1 >= 0.f ? v1 : 0.01f * v1;
        ((__nv_bfloat162*)(h0 + (size_t)(e0 + i) * 256))[cp] = __floats2bfloat162_rn(v0, v1);
    }
}

// ============================ fused 8 mid layers + head (paired groups, named barriers) ============================
// CTA = 128 edges, 512 threads, warp grid 4(M)x4(N): warp = 32 edges x 64 cols.
// Activations in SMEM A region [0,64K). Weight ring 4x32KB; slots committed in PAIRS
// (group = 64KB = half layer). Per group: cp_wait<0> + ONE __syncthreads + issue next group.
// Pre-epilogue sync is a named barrier over the 128 threads sharing an M-block.
// Barriers per layer: 2 full + 1 named (vs 5 full in R10).
__global__ void __launch_bounds__(512, 1)
fused_mid(const __nv_bfloat16* __restrict__ h0, const __nv_bfloat16* __restrict__ Bm,
          const float* __restrict__ bm, const float* __restrict__ Wl,
          const float* __restrict__ bl, float* __restrict__ out) {
    extern __shared__ char smem[];
    const uint32_t sb = smem_u32(smem);
    constexpr uint32_t RINGOFF = 65536;               // ring: 4 x 32KB at [64K, 192K)
    constexpr uint32_t PARAM = 65536 + 131072;
    float* sbias = (float*)(smem + PARAM);            // 8 x 256 fp32
    float* sWl   = (float*)(smem + PARAM + 8192);     // 256 x 3 fp32
    float* sbl   = (float*)(smem + PARAM + 8192 + 3072);

    const int tid = threadIdx.x, lane = tid & 31, warp = tid >> 5;
    const int warp_m = warp >> 2;                     // 0..3 -> M offset *32
    const int warp_n = warp & 3;                      // 0..3 -> N offset *64
    const size_t m0 = (size_t)blockIdx.x * 128;

    for (int i = tid; i < 2048; i += 512) sbias[i] = bm[i];
    for (int i = tid; i < 768; i += 512) sWl[i] = Wl[i];
    if (tid < 3) sbl[tid] = bl[tid];

    // single slot loader: slot s -> layer s>>2, K-quarter s&3, region s&3
    auto loadB = [&](int s) {
        const uint32_t base = sb + RINGOFF + (uint32_t)(s & 3) * 32768u;
        const __nv_bfloat16* src = Bm + (size_t)(s >> 2) * 65536 + (s & 3) * 64;
        #pragma unroll
        for (int i = 0; i < 4; i++) {
            int idx = tid + i * 512;
            int r = idx >> 3, c8 = idx & 7;
            cp16(base + r * 128 + ((c8 ^ (r & 7)) << 4), src + (size_t)r * 256 + c8 * 8);
        }
    };

    // A tile (h0, 128x256) -> A region as 4 chunks of [128][64], XOR swizzle
    #pragma unroll
    for (int kc = 0; kc < 4; kc++)
        #pragma unroll
        for (int i = 0; i < 2; i++) {
            int idx = tid + i * 512;
            int r = idx >> 3, c8 = idx & 7;
            cp16(sb + kc * 16384 + r * 128 + ((c8 ^ (r & 7)) << 4),
                 h0 + (m0 + r) * 256 + kc * 64 + c8 * 8);
        }
    // group 0 = slots {0,1} committed together with A
    loadB(0); loadB(1);
    cp_commit();                 // C1 = A + group0

    const int g = lane >> 2, j = lane & 3;
    const int rr_lo = ((lane >> 4) << 3) + (lane & 7);
    const int ar_lo = warp_m * 32 + (lane & 15);

    for (int l = 0; l < 8; ++l) {
        float acc[2][8][4];
        #pragma unroll
        for (int nt = 0; nt < 8; nt++) {
            float2 bb = *(const float2*)(sbias + (l << 8) + warp_n * 64 + 8 * nt + 2 * j);
            #pragma unroll
            for (int mi = 0; mi < 2; mi++) {
                acc[mi][nt][0] = bb.x; acc[mi][nt][1] = bb.y;
                acc[mi][nt][2] = bb.x; acc[mi][nt][3] = bb.y;
            }
        }
        #pragma unroll
        for (int gg = 0; gg < 2; gg++) {
            const int grp = 2 * l + gg;              // group index 0..15
            cp_wait<0>();                            // group grp loaded (issued one window ago)
            __syncthreads();                         // visibility + region-reuse safety
            if (grp + 1 < 16) { loadB(2 * (grp + 1)); loadB(2 * (grp + 1) + 1); }
            cp_commit();
            #pragma unroll
            for (int khh = 0; khh < 2; khh++) {
                const int kh = gg * 2 + khh;
                const int s = l * 4 + kh;
                const uint32_t bbase = sb + RINGOFF + (uint32_t)(s & 3) * 32768u;
                const uint32_t achk = sb + kh * 16384;
                #pragma unroll
                for (int ksl = 0; ksl < 4; ksl++) {
                    const int cca = ksl * 2 + (lane >> 4);
                    uint32_t a0[4], a1[4];
                    int r0 = ar_lo;
                    ldm_x4(a0, achk + r0 * 128 + ((cca ^ (r0 & 7)) << 4));
                    int r1 = ar_lo + 16;
                    ldm_x4(a1, achk + r1 * 128 + ((cca ^ (r1 & 7)) << 4));
                    const int ccb = ksl * 2 + ((lane >> 3) & 1);
                    #pragma unroll
                    for (int bt = 0; bt < 4; bt++) {
                        int rr = warp_n * 64 + bt * 16 + rr_lo;
                        uint32_t bf[4];
                        ldm_x4(bf, bbase + rr * 128 + ((ccb ^ (rr & 7)) << 4));
                        mma_bf16(acc[0][2 * bt],     a0, bf);
                        mma_bf16(acc[0][2 * bt + 1], a0, bf + 2);
                        mma_bf16(acc[1][2 * bt],     a1, bf);
                        mma_bf16(acc[1][2 * bt + 1], a1, bf + 2);
                    }
                }
            }
        }
        // named barrier: only the 4 warps sharing this M-block must finish their A reads
        asm volatile("bar.sync %0, %1;" :: "r"(1 + warp_m), "r"(128) : "memory");
        // epilogue: leaky + bf16 + STS back into A region (own M-block rows only)
        #pragma unroll
        for (int mi = 0; mi < 2; mi++) {
            const int r  = warp_m * 32 + mi * 16 + g;
            const int r2 = r + 8;
            #pragma unroll
            for (int nt = 0; nt < 8; nt++) {
                float v0 = acc[mi][nt][0], v1 = acc[mi][nt][1];
                float v2 = acc[mi][nt][2], v3 = acc[mi][nt][3];
                v0 = v0 >= 0.f ? v0 : 0.01f * v0;  v1 = v1 >= 0.f ? v1 : 0.01f * v1;
                v2 = v2 >= 0.f ? v2 : 0.01f * v2;  v3 = v3 >= 0.f ? v3 : 0.01f * v3;
                __nv_bfloat162 p0 = __floats2bfloat162_rn(v0, v1);
                __nv_bfloat162 p1 = __floats2bfloat162_rn(v2, v3);
                const int c = warp_n * 64 + nt * 8;
                const int kc = c >> 6, c8s = (c >> 3) & 7;
                *(uint32_t*)(smem + kc * 16384 + r * 128 + ((c8s ^ (r & 7)) << 4) + 4 * j) =
                    *(uint32_t*)&p0;
                *(uint32_t*)(smem + kc * 16384 + r2 * 128 + ((c8s ^ (r2 & 7)) << 4) + 4 * j) =
                    *(uint32_t*)&p1;
            }
        }
        // next group's full __syncthreads orders these STS before the next layer's LDSMs
    }
    __syncthreads();

    // ---- fused head (warps 0-7): logits + log_softmax ----
    if (warp < 8) {
        uint32_t pa[32][2];
        #pragma unroll
        for (int s = 0; s < 16; s++) {
            int rr = warp * 16 + (lane & 15);
            int cc = (s & 3) * 2 + (lane >> 4);
            uint32_t f[4];
            ldm_x4(f, sb + (s >> 2) * 16384 + rr * 128 + ((cc ^ (rr & 7)) << 4));
            pa[2 * s][0] = f[0]; pa[2 * s][1] = f[1];
            pa[2 * s + 1][0] = f[2]; pa[2 * s + 1][1] = f[3];
        }
        float a3[2][3] = {{0.f, 0.f, 0.f}, {0.f, 0.f, 0.f}};
        #pragma unroll
        for (int t = 0; t < 32; t++) {
            float2 x = __bfloat1622float2(*(__nv_bfloat162*)&pa[t][0]);
            float2 y = __bfloat1622float2(*(__nv_bfloat162*)&pa[t][1]);
            const int c0 = 8 * t + 2 * j;
            float w00 = sWl[c0 * 3 + 0], w01 = sWl[c0 * 3 + 1], w02 = sWl[c0 * 3 + 2];
            float w10 = sWl[c0 * 3 + 3], w11 = sWl[c0 * 3 + 4], w12 = sWl[c0 * 3 + 5];
            a3[0][0] += x.x * w00 + x.y * w10;
            a3[0][1] += x.x * w01 + x.y * w11;
            a3[0][2] += x.x * w02 + x.y * w12;
            a3[1][0] += y.x * w00 + y.y * w10;
            a3[1][1] += y.x * w01 + y.y * w11;
            a3[1][2] += y.x * w02 + y.y * w12;
        }
        #pragma unroll
        for (int off = 1; off <= 2; off <<= 1) {
            #pragma unroll
            for (int r = 0; r < 2; r++)
                #pragma unroll
                for (int c = 0; c < 3; c++)
                    a3[r][c] += __shfl_xor_sync(0xffffffffu, a3[r][c], off);
        }
        if (j == 0) {
            const float bb0 = sbl[0], bb1 = sbl[1], bb2 = sbl[2];
            #pragma unroll
            for (int r = 0; r < 2; r++) {
                size_t e = m0 + warp * 16 + g + 8 * r;
                float l0 = a3[r][0] + bb0, l1 = a3[r][1] + bb1, l2 = a3[r][2] + bb2;
                float m = fmaxf(l0, fmaxf(l1, l2));
                float ls = m + logf(expf(l0 - m) + expf(l1 - m) + expf(l2 - m));
                out[e * 3 + 0] = l0 - ls;
                out[e * 3 + 1] = l1 - ls;
                out[e * 3 + 2] = l2 - ls;
            }
        }
    }
}

// ============================ host ============================
extern "C" void kernel_launch(void* const* d_in, const int* in_sizes, int n_in,
                              void* d_out, int out_size) {
    const float* x  = (const float*)d_in[0];
    const int*   ei = (const int*)d_in[1];
    const float* ea = (const float*)d_in[2];
    const float* Wx = (const float*)d_in[3];
    const float* bx = (const float*)d_in[4];
    const float* W0 = (const float*)d_in[5];
    const float* b0 = (const float*)d_in[6];
    const float* Wm = (const float*)d_in[7];
    const float* bm = (const float*)d_in[8];
    const float* Wl = (const float*)d_in[9];
    const float* bl = (const float*)d_in[10];
    float* out = (float*)d_out;

    void* p;
    cudaGetSymbolAddress(&p, g_xb);    __nv_bfloat16* xb    = (__nv_bfloat16*)p;
    cudaGetSymbolAddress(&p, g_hnode); __nv_bfloat16* hnode = (__nv_bfloat16*)p;
    cudaGetSymbolAddress(&p, g_grow);  __nv_bfloat16* grow  = (__nv_bfloat16*)p;
    cudaGetSymbolAddress(&p, g_gcol);  __nv_bfloat16* gcol  = (__nv_bfloat16*)p;
    cudaGetSymbolAddress(&p, g_h0);    __nv_bfloat16* h0p   = (__nv_bfloat16*)p;
    cudaGetSymbolAddress(&p, g_Bx);    __nv_bfloat16* Bx    = (__nv_bfloat16*)p;
    cudaGetSymbolAddress(&p, g_B0a);   __nv_bfloat16* B0a   = (__nv_bfloat16*)p;
    cudaGetSymbolAddress(&p, g_B0b);   __nv_bfloat16* B0b   = (__nv_bfloat16*)p;
    cudaGetSymbolAddress(&p, g_Bm);    __nv_bfloat16* Bm    = (__nv_bfloat16*)p;

    constexpr int SMEM = 65536;
    constexpr int FSMEM = 65536 + 131072 + 8192 + 3072 + 16;   // 207,904
    cudaFuncSetAttribute(gemm_mma<256, 128, true,  true,  false>, cudaFuncAttributeMaxDynamicSharedMemorySize, SMEM);
    cudaFuncSetAttribute(gemm_mma<128, 256, false, false, true >, cudaFuncAttributeMaxDynamicSharedMemorySize, SMEM);
    cudaFuncSetAttribute(fused_mid, cudaFuncAttributeMaxDynamicSharedMemorySize, FSMEM);

    // 1: idx detect + x -> bf16
    prep_misc<<<4096, 256>>>(x, (const unsigned*)ei);
    // 2: all weight transposes
    prep_W<<<608, dim3(32, 8)>>>(Wx, W0, Wm);
    // 3: node MLP: h_node = leaky(x @ Wx + bx)
    gemm_mma<256, 128, true, true, false><<<dim3(NNODES / 128, 1, 1), 256, SMEM>>>(
        xb, Bx, nullptr, bx, hnode, nullptr);
    // 4: node-level edge-GEMM precompute: grow/gcol in one dual launch
    gemm_mma<128, 256, false, false, true><<<dim3(NNODES / 128, 2, 2), 256, SMEM>>>(
        hnode, B0a, B0b, nullptr, grow, gcol);
    // 5: gather + ea matvec + combine + leaky -> h0
    gather_combine_ea<<<NEDGES / 64, 256>>>(ei, ea, W0, b0, grow, gcol, h0p);
    // 6: fused: 8 hidden layers + head + log_softmax   (<- ncu capture target)
    fused_mid<<<NEDGES / 128, 512, FSMEM>>>(h0p, Bm, bm, Wl, bl, out);
}